// round 1
// baseline (speedup 1.0000x reference)
#include <cuda_runtime.h>
#include <math.h>

#define BB 4
#define CC 256
#define NN 8192
#define DA 64
#define RSM 128
#define RG 16
#define RR 2048       // RSM*RG
#define NTILES 64     // NN/128

// ---------------- scratch (static device globals; no allocation) ----------------
__device__ float g_qkv[(size_t)BB*NN*384];     // [b][n][0:64 q,64:128 k,128:384 v]
__device__ float g_qp [(size_t)BB*NN*RSM];
__device__ float g_kp [(size_t)BB*NN*RSM];
__device__ float g_phi[(size_t)BB*NN*RG];
__device__ float g_kv [(size_t)BB*RR*CC];
__device__ float g_ksum[(size_t)BB*RR];
__device__ float g_denom[(size_t)BB*NN];
__device__ float g_fsa[(size_t)BB*NN*CC];
__device__ float g_h  [(size_t)BB*CC*NN];
__device__ float g_psum  [(size_t)BB*NTILES*CC];
__device__ float g_psumsq[(size_t)BB*NTILES*CC];
__device__ float g_scale[CC];
__device__ float g_bias [CC];

#define ROWQ(g,m) (((m)<4) ? ((g)*4+(m)) : (64+(g)*4+((m)-4)))

__device__ __forceinline__ void mma16(const float (*As)[132], const float (*Bs)[132],
                                      float acc[8][8], int ty, int tx){
    #pragma unroll
    for(int kk=0;kk<16;kk++){
        float a[8], bv[8];
        *(float4*)(a)    = *(const float4*)&As[kk][ty*4];
        *(float4*)(a+4)  = *(const float4*)&As[kk][64+ty*4];
        *(float4*)(bv)   = *(const float4*)&Bs[kk][tx*4];
        *(float4*)(bv+4) = *(const float4*)&Bs[kk][64+tx*4];
        #pragma unroll
        for(int m=0;m<8;m++)
            #pragma unroll
            for(int n=0;n<8;n++)
                acc[m][n]=fmaf(a[m],bv[n],acc[m][n]);
    }
}

// ---------------- kernel 1: QKV = X^T @ [Wq;Wk;Wv]^T (q,k scaled) ----------------
__global__ __launch_bounds__(256) void qkv_gemm(const float* __restrict__ x,
    const float* __restrict__ Wq, const float* __restrict__ Wk, const float* __restrict__ Wv)
{
    __shared__ float As[16][132];  // [kk][nn]
    __shared__ float Bs[16][132];  // [kk][oo]
    int nt=blockIdx.x, ot=blockIdx.y, b=blockIdx.z;
    int n0=nt*128, o0=ot*128;
    int tid=threadIdx.x, ty=tid>>4, tx=tid&15;
    float acc[8][8]={};
    for(int c0=0;c0<256;c0+=16){
        #pragma unroll
        for(int l=0;l<2;l++){
            int f4=tid+l*256;
            int kk=f4>>5, n4=(f4&31)<<2;
            *(float4*)&As[kk][n4] = *(const float4*)(x + ((size_t)b*CC + c0+kk)*NN + n0+n4);
            int oo=f4>>2, kc=(f4&3)<<2;
            int o=o0+oo;
            const float* wr = (o<64)? (Wq+(size_t)o*CC) : ((o<128)? (Wk+(size_t)(o-64)*CC) : (Wv+(size_t)(o-128)*CC));
            float4 w=*(const float4*)(wr + c0+kc);
            Bs[kc+0][oo]=w.x; Bs[kc+1][oo]=w.y; Bs[kc+2][oo]=w.z; Bs[kc+3][oo]=w.w;
        }
        __syncthreads();
        mma16(As,Bs,acc,ty,tx);
        __syncthreads();
    }
    float s = (ot==0)? 0.3535533905932738f : 1.0f;   // 64^-0.25 for q,k
    #pragma unroll
    for(int m=0;m<8;m++){
        int n=n0+ROWQ(ty,m);
        size_t base=((size_t)b*NN+n)*384 + o0;
        float4 v0={acc[m][0]*s,acc[m][1]*s,acc[m][2]*s,acc[m][3]*s};
        float4 v1={acc[m][4]*s,acc[m][5]*s,acc[m][6]*s,acc[m][7]*s};
        *(float4*)&g_qkv[base+tx*4]=v0;
        *(float4*)&g_qkv[base+64+tx*4]=v1;
    }
}

// ---------------- kernel 2: feature maps (q_p, k_p) and geo RFF (phi) -----------
__global__ __launch_bounds__(128) void feat_kernel(const float* __restrict__ pos,
    const float* __restrict__ P,  const float* __restrict__ Wg1, const float* __restrict__ bg1,
    const float* __restrict__ Wg2,const float* __restrict__ bg2, const float* __restrict__ logtau,
    const float* __restrict__ omega)
{
    __shared__ float Ps[4096];     // [o][m] 64x64
    __shared__ float Om[256];
    __shared__ float sWg1[48], sbg1[16], sWg2[256], sbg2[16];
    int tid=threadIdx.x;
    for(int i=tid;i<4096;i+=128) Ps[i]=P[i];
    for(int i=tid;i<256;i+=128){ Om[i]=omega[i]; sWg2[i]=Wg2[i]; }
    if(tid<48) sWg1[tid]=Wg1[tid];
    if(tid<16){ sbg1[tid]=bg1[tid]; sbg2[tid]=bg2[tid]; }
    __syncthreads();

    int b=blockIdx.y;
    int n=blockIdx.x*128 + tid;
    size_t bn=(size_t)b*NN + n;

    // ---- phi (geo RFF) ----
    float lt=logtau[0];
    float tau=log1pf(expf(lt)) + 1e-6f;
    float s2t=sqrtf(2.0f*tau);
    float p0=pos[bn*3+0], p1=pos[bn*3+1], p2=pos[bn*3+2];
    float g1[16], z[16];
    #pragma unroll
    for(int d=0;d<16;d++){
        float t=fmaf(sWg1[d*3],p0,fmaf(sWg1[d*3+1],p1,fmaf(sWg1[d*3+2],p2,sbg1[d])));
        g1[d]=fmaxf(t,0.0f);
    }
    float zn=0.0f;
    #pragma unroll
    for(int d=0;d<16;d++){
        float t=sbg2[d];
        #pragma unroll
        for(int e=0;e<16;e++) t=fmaf(sWg2[d*16+e],g1[e],t);
        z[d]=t*s2t;
        zn=fmaf(z[d],z[d],zn);
    }
    zn*=0.5f;
    #pragma unroll
    for(int r=0;r<16;r++){
        float t=0.0f;
        #pragma unroll
        for(int d=0;d<16;d++) t=fmaf(z[d],Om[d*16+r],t);
        g_phi[bn*16+r]=expf(t-zn)*0.25f;   // 16^-0.5
    }

    // ---- softmax feature maps for q and k ----
    const float* row = g_qkv + bn*384;
    const float fs = 0.08838834764831845f; // (2*64)^-0.5
    for(int which=0;which<2;which++){
        const float* qr = row + which*64;
        float proj[64];
        #pragma unroll
        for(int m=0;m<64;m++) proj[m]=0.0f;
        for(int o=0;o<64;o++){
            float qo=qr[o];
            #pragma unroll
            for(int m=0;m<64;m++) proj[m]=fmaf(qo,Ps[o*64+m],proj[m]);
        }
        float M=0.0f;
        #pragma unroll
        for(int m=0;m<64;m++) M=fmaxf(M,fabsf(proj[m]));
        float* dst=(which==0? g_qp : g_kp) + bn*128;
        #pragma unroll
        for(int m=0;m<64;m++){
            dst[m]    = expf(proj[m]-M)*fs + 1e-6f;
            dst[64+m] = expf(-proj[m]-M)*fs + 1e-6f;
        }
    }
}

// ---------------- kernel 3: kv[b][i*16+j][c] = sum_n kp[n,i]*phi[n,j]*v[n,c] ----
__global__ __launch_bounds__(256) void kv_gemm()
{
    __shared__ float As[16][132];   // [kk][i]
    __shared__ float Bs[16][132];   // [kk][c]
    int j=blockIdx.x, ct=blockIdx.y, b=blockIdx.z;
    int tid=threadIdx.x, ty=tid>>4, tx=tid&15;
    const float* kp = g_kp  + (size_t)b*NN*128;
    const float* ph = g_phi + (size_t)b*NN*16;
    const float* vv = g_qkv + (size_t)b*NN*384 + 128 + (size_t)ct*128;

    float acc[8][8]={};
    float ks[8]={};
    float4 ra[2], rb[2]; float rp[2];
    int kkL[2], q4L[2];
    #pragma unroll
    for(int l=0;l<2;l++){ int f4=tid+l*256; kkL[l]=f4>>5; q4L[l]=(f4&31)<<2; }
    #pragma unroll
    for(int l=0;l<2;l++){
        rp[l]=ph[(size_t)kkL[l]*16 + j];
        ra[l]=*(const float4*)(kp + (size_t)kkL[l]*128 + q4L[l]);
        rb[l]=*(const float4*)(vv + (size_t)kkL[l]*384 + q4L[l]);
    }
    for(int n0=0;n0<NN;n0+=16){
        #pragma unroll
        for(int l=0;l<2;l++){
            float4 a=ra[l]; float p=rp[l];
            a.x*=p; a.y*=p; a.z*=p; a.w*=p;
            *(float4*)&As[kkL[l]][q4L[l]]=a;
            *(float4*)&Bs[kkL[l]][q4L[l]]=rb[l];
        }
        __syncthreads();
        int n1=n0+16;
        if(n1<NN){
            #pragma unroll
            for(int l=0;l<2;l++){
                int n=n1+kkL[l];
                rp[l]=ph[(size_t)n*16 + j];
                ra[l]=*(const float4*)(kp + (size_t)n*128 + q4L[l]);
                rb[l]=*(const float4*)(vv + (size_t)n*384 + q4L[l]);
            }
        }
        #pragma unroll
        for(int kk=0;kk<16;kk++){
            float a[8], bv[8];
            *(float4*)(a)    = *(float4*)&As[kk][ty*4];
            *(float4*)(a+4)  = *(float4*)&As[kk][64+ty*4];
            *(float4*)(bv)   = *(float4*)&Bs[kk][tx*4];
            *(float4*)(bv+4) = *(float4*)&Bs[kk][64+tx*4];
            if(tx==0){
                #pragma unroll
                for(int m=0;m<8;m++) ks[m]+=a[m];
            }
            #pragma unroll
            for(int m=0;m<8;m++)
                #pragma unroll
                for(int n=0;n<8;n++)
                    acc[m][n]=fmaf(a[m],bv[n],acc[m][n]);
        }
        __syncthreads();
    }
    #pragma unroll
    for(int m=0;m<8;m++){
        int i=ROWQ(ty,m);
        int r=i*16+j;
        size_t base=((size_t)b*RR+r)*CC + (size_t)ct*128;
        float4 v0={acc[m][0],acc[m][1],acc[m][2],acc[m][3]};
        float4 v1={acc[m][4],acc[m][5],acc[m][6],acc[m][7]};
        *(float4*)&g_kv[base+tx*4]=v0;
        *(float4*)&g_kv[base+64+tx*4]=v1;
        if(tx==0 && ct==0) g_ksum[(size_t)b*RR+r]=ks[m];
    }
}

// ---------------- kernel 3.5: denom[b][n] = Phi_q[n]·k_sum + eps ----------------
__global__ __launch_bounds__(256) void denom_kernel()
{
    __shared__ float ks[2048];
    int b=blockIdx.y;
    for(int i=threadIdx.x;i<2048;i+=256) ks[i]=g_ksum[(size_t)b*RR+i];
    __syncthreads();
    int n=blockIdx.x*256 + threadIdx.x;
    size_t bn=(size_t)b*NN+n;
    float ph[16];
    #pragma unroll
    for(int r=0;r<16;r++) ph[r]=g_phi[bn*16+r];
    float d=0.0f;
    for(int i=0;i<128;i++){
        float t=0.0f;
        #pragma unroll
        for(int jj=0;jj<16;jj++) t=fmaf(ks[i*16+jj],ph[jj],t);
        d=fmaf(g_qp[bn*128+i],t,d);
    }
    g_denom[bn]=d+1e-6f;
}

// ---------------- kernel 4: fsa[b][n][c] = (Phi_q @ kv)/denom --------------------
__global__ __launch_bounds__(256) void fsa_gemm()
{
    __shared__ float As[16][132];   // [j][nn]
    __shared__ float Bs[16][132];   // [j][cc]
    int nt=blockIdx.x, ct=blockIdx.y, b=blockIdx.z;
    int n0=nt*128;
    int tid=threadIdx.x, ty=tid>>4, tx=tid&15;
    const float* qp  = g_qp  + ((size_t)b*NN+n0)*128;
    const float* ph  = g_phi + ((size_t)b*NN+n0)*16;
    const float* kvp = g_kv  + (size_t)b*RR*CC + (size_t)ct*128;

    float acc[8][8]={};
    int nnL[2], j4L[2], kkL[2], c4L[2];
    #pragma unroll
    for(int l=0;l<2;l++){
        int f4=tid+l*256;
        nnL[l]=f4>>2; j4L[l]=(f4&3)<<2;
        kkL[l]=f4>>5; c4L[l]=(f4&31)<<2;
    }
    float4 rp4[2], rbv[2]; float rq[2];
    #pragma unroll
    for(int l=0;l<2;l++){
        rp4[l]=*(const float4*)(ph + (size_t)nnL[l]*16 + j4L[l]);   // invariant over K
        rq[l] = qp[(size_t)nnL[l]*128 + 0];
        rbv[l]=*(const float4*)(kvp + (size_t)kkL[l]*CC + c4L[l]);
    }
    for(int i=0;i<128;i++){
        #pragma unroll
        for(int l=0;l<2;l++){
            float q=rq[l];
            As[j4L[l]+0][nnL[l]]=rp4[l].x*q;
            As[j4L[l]+1][nnL[l]]=rp4[l].y*q;
            As[j4L[l]+2][nnL[l]]=rp4[l].z*q;
            As[j4L[l]+3][nnL[l]]=rp4[l].w*q;
            *(float4*)&Bs[kkL[l]][c4L[l]]=rbv[l];
        }
        __syncthreads();
        if(i+1<128){
            #pragma unroll
            for(int l=0;l<2;l++){
                rq[l] = qp[(size_t)nnL[l]*128 + (i+1)];
                rbv[l]= *(const float4*)(kvp + (size_t)((i+1)*16+kkL[l])*CC + c4L[l]);
            }
        }
        mma16(As,Bs,acc,ty,tx);
        __syncthreads();
    }
    #pragma unroll
    for(int m=0;m<8;m++){
        int n=n0+ROWQ(ty,m);
        float inv=1.0f/g_denom[(size_t)b*NN+n];
        size_t base=((size_t)b*NN+n)*CC + (size_t)ct*128;
        float4 v0={acc[m][0]*inv,acc[m][1]*inv,acc[m][2]*inv,acc[m][3]*inv};
        float4 v1={acc[m][4]*inv,acc[m][5]*inv,acc[m][6]*inv,acc[m][7]*inv};
        *(float4*)&g_fsa[base+tx*4]=v0;
        *(float4*)&g_fsa[base+64+tx*4]=v1;
    }
}

// ---------------- kernel 5: h = Wp @ (x - fsa^T), + BN partial sums --------------
__global__ __launch_bounds__(256) void h_gemm(const float* __restrict__ x, const float* __restrict__ Wp)
{
    __shared__ float As[16][132];   // [kc][oo] = Wp[o][c]
    __shared__ float Bs[16][132];   // [kc][nn] = x - fsa
    __shared__ float red[128][17];
    int ot=blockIdx.x, nt=blockIdx.y, b=blockIdx.z;
    int o0=ot*128, n0=nt*128;
    int tid=threadIdx.x, ty=tid>>4, tx=tid&15;
    float acc[8][8]={};
    for(int c0=0;c0<256;c0+=16){
        #pragma unroll
        for(int l=0;l<2;l++){
            int f4=tid+l*256;
            int oo=f4>>2, kc=(f4&3)<<2;
            float4 w=*(const float4*)(Wp + (size_t)(o0+oo)*256 + c0+kc);
            As[kc+0][oo]=w.x; As[kc+1][oo]=w.y; As[kc+2][oo]=w.z; As[kc+3][oo]=w.w;
            float4 f=*(const float4*)(g_fsa + ((size_t)b*NN + n0+oo)*256 + c0+kc);
            Bs[kc+0][oo]=-f.x; Bs[kc+1][oo]=-f.y; Bs[kc+2][oo]=-f.z; Bs[kc+3][oo]=-f.w;
        }
        __syncthreads();
        #pragma unroll
        for(int l=0;l<2;l++){
            int f4=tid+l*256;
            int kk=f4>>5, n4=(f4&31)<<2;
            float4 xv=*(const float4*)(x + ((size_t)b*CC + c0+kk)*NN + n0+n4);
            float4 cur=*(float4*)&Bs[kk][n4];
            cur.x+=xv.x; cur.y+=xv.y; cur.z+=xv.z; cur.w+=xv.w;
            *(float4*)&Bs[kk][n4]=cur;
        }
        __syncthreads();
        mma16(As,Bs,acc,ty,tx);
        __syncthreads();
    }
    // store h
    #pragma unroll
    for(int m=0;m<8;m++){
        int o=o0+ROWQ(ty,m);
        size_t base=((size_t)b*CC+o)*NN + n0;
        float4 v0={acc[m][0],acc[m][1],acc[m][2],acc[m][3]};
        float4 v1={acc[m][4],acc[m][5],acc[m][6],acc[m][7]};
        *(float4*)&g_h[base+tx*4]=v0;
        *(float4*)&g_h[base+64+tx*4]=v1;
    }
    // deterministic BN partials: per-o sums over this block's 128 n
    float s[8], s2[8];
    #pragma unroll
    for(int m=0;m<8;m++){
        float a=0.f,a2=0.f;
        #pragma unroll
        for(int n=0;n<8;n++){ a+=acc[m][n]; a2=fmaf(acc[m][n],acc[m][n],a2); }
        s[m]=a; s2[m]=a2;
    }
    #pragma unroll
    for(int m=0;m<8;m++) red[ROWQ(ty,m)][tx]=s[m];
    __syncthreads();
    if(tid<128){
        float t=0.f;
        #pragma unroll
        for(int k=0;k<16;k++) t+=red[tid][k];
        g_psum[((size_t)b*NTILES+nt)*CC + o0 + tid]=t;
    }
    __syncthreads();
    #pragma unroll
    for(int m=0;m<8;m++) red[ROWQ(ty,m)][tx]=s2[m];
    __syncthreads();
    if(tid<128){
        float t=0.f;
        #pragma unroll
        for(int k=0;k<16;k++) t+=red[tid][k];
        g_psumsq[((size_t)b*NTILES+nt)*CC + o0 + tid]=t;
    }
}

// ---------------- kernel 6: BN stats -> scale/bias -------------------------------
__global__ void stats_kernel(const float* __restrict__ gamma, const float* __restrict__ beta)
{
    int o=threadIdx.x;
    float s=0.f,s2=0.f;
    for(int t=0;t<BB*NTILES;t++){
        s +=g_psum  [(size_t)t*CC+o];
        s2+=g_psumsq[(size_t)t*CC+o];
    }
    const float inv=1.0f/(float)((size_t)BB*NN);
    float mean=s*inv;
    float var=s2*inv - mean*mean;
    float sc=gamma[o]*rsqrtf(var+1e-5f);
    g_scale[o]=sc;
    g_bias[o]=beta[o]-mean*sc;
}

// ---------------- kernel 7: out = relu(BN(h)) + x --------------------------------
__global__ __launch_bounds__(256) void final_kernel(const float* __restrict__ x, float* __restrict__ out)
{
    size_t i4=(size_t)blockIdx.x*256 + threadIdx.x;
    size_t f=i4*4;
    int c=(int)((f/NN)%CC);
    float sc=g_scale[c], bi=g_bias[c];
    float4 h=*(const float4*)(g_h+f);
    float4 xv=*(const float4*)(x+f);
    float4 o;
    o.x=fmaxf(fmaf(h.x,sc,bi),0.0f)+xv.x;
    o.y=fmaxf(fmaf(h.y,sc,bi),0.0f)+xv.y;
    o.z=fmaxf(fmaf(h.z,sc,bi),0.0f)+xv.z;
    o.w=fmaxf(fmaf(h.w,sc,bi),0.0f)+xv.w;
    *(float4*)(out+f)=o;
}

// ---------------- launch ----------------------------------------------------------
extern "C" void kernel_launch(void* const* d_in, const int* in_sizes, int n_in,
                              void* d_out, int out_size)
{
    const float* x      =(const float*)d_in[0];
    const float* pos    =(const float*)d_in[1];
    const float* Wq     =(const float*)d_in[2];
    const float* Wk     =(const float*)d_in[3];
    const float* Wv     =(const float*)d_in[4];
    const float* proj_sm=(const float*)d_in[5];
    const float* Wg1    =(const float*)d_in[6];
    const float* bg1    =(const float*)d_in[7];
    const float* Wg2    =(const float*)d_in[8];
    const float* bg2    =(const float*)d_in[9];
    const float* log_tau=(const float*)d_in[10];
    const float* omega  =(const float*)d_in[11];
    const float* Wp     =(const float*)d_in[12];
    const float* gamma  =(const float*)d_in[13];
    const float* beta   =(const float*)d_in[14];
    float* out=(float*)d_out;

    qkv_gemm   <<<dim3(64,3,BB),256>>>(x,Wq,Wk,Wv);
    feat_kernel<<<dim3(64,BB),128>>>(pos,proj_sm,Wg1,bg1,Wg2,bg2,log_tau,omega);
    kv_gemm    <<<dim3(16,2,BB),256>>>();
    denom_kernel<<<dim3(32,BB),256>>>();
    fsa_gemm   <<<dim3(64,2,BB),256>>>();
    h_gemm     <<<dim3(2,64,BB),256>>>(x,Wp);
    stats_kernel<<<1,256>>>(gamma,beta);
    final_kernel<<<8192,256>>>(x,out);
}

// round 3
// speedup vs baseline: 1.8127x; 1.8127x over previous
#include <cuda_runtime.h>
#include <math.h>
#include <stdint.h>

#define BB 4
#define CC 256
#define NN 8192
#define RSM 128
#define RG 16
#define RR 2048       // RSM*RG
#define NTILES 64     // NN/128

// ---------------- scratch (static device globals; no allocation) ----------------
__device__ float g_qkv[(size_t)BB*NN*384];     // [b][n][0:64 q,64:128 k,128:384 v]
__device__ float g_qp [(size_t)BB*NN*RSM];
__device__ float g_kp [(size_t)BB*NN*RSM];
__device__ float g_phi[(size_t)BB*NN*RG];
__device__ float g_kv [(size_t)BB*RR*CC];
__device__ float g_ksum[(size_t)BB*RR];
__device__ float g_kspart[(size_t)BB*32*RR];
__device__ float g_denom[(size_t)BB*NN];
__device__ float g_fsa[(size_t)BB*NN*CC];
__device__ float g_h  [(size_t)BB*CC*NN];
__device__ float g_psum  [(size_t)BB*NTILES*CC];
__device__ float g_psumsq[(size_t)BB*NTILES*CC];
__device__ float g_scale[CC];
__device__ float g_bias [CC];

#define ROWQ(g,m) (((m)<4) ? ((g)*4+(m)) : (64+(g)*4+((m)-4)))

// ================= tf32 warp-MMA helpers (sm_80+, family-portable) ==============
__device__ __forceinline__ uint32_t f2tf32(float f){
    uint32_t r; asm("cvt.rna.tf32.f32 %0, %1;" : "=r"(r) : "f"(f)); return r;
}
__device__ __forceinline__ void mma_tf32(float* c,
    uint32_t a0, uint32_t a1, uint32_t a2, uint32_t a3, uint32_t b0, uint32_t b1){
    asm volatile(
      "mma.sync.aligned.m16n8k8.row.col.f32.tf32.tf32.f32 "
      "{%0,%1,%2,%3},{%4,%5,%6,%7},{%8,%9},{%0,%1,%2,%3};"
      : "+f"(c[0]),"+f"(c[1]),"+f"(c[2]),"+f"(c[3])
      : "r"(a0),"r"(a1),"r"(a2),"r"(a3),"r"(b0),"r"(b1));
}

// =========================== FFMA helper =========================================
__device__ __forceinline__ void mma16(const float (*As)[132], const float (*Bs)[132],
                                      float acc[8][8], int ty, int tx){
    #pragma unroll
    for(int kk=0;kk<16;kk++){
        float a[8], bv[8];
        *(float4*)(a)    = *(const float4*)&As[kk][ty*4];
        *(float4*)(a+4)  = *(const float4*)&As[kk][64+ty*4];
        *(float4*)(bv)   = *(const float4*)&Bs[kk][tx*4];
        *(float4*)(bv+4) = *(const float4*)&Bs[kk][64+tx*4];
        #pragma unroll
        for(int m=0;m<8;m++)
            #pragma unroll
            for(int n=0;n<8;n++)
                acc[m][n]=fmaf(a[m],bv[n],acc[m][n]);
    }
}

// ---------------- kernel 1: QKV = X^T @ [Wq;Wk;Wv]^T (q,k scaled) ----------------
__global__ __launch_bounds__(256) void qkv_gemm(const float* __restrict__ x,
    const float* __restrict__ Wq, const float* __restrict__ Wk, const float* __restrict__ Wv)
{
    __shared__ float As[16][132];
    __shared__ float Bs[16][132];
    int nt=blockIdx.x, ot=blockIdx.y, b=blockIdx.z;
    int n0=nt*128, o0=ot*128;
    int tid=threadIdx.x, ty=tid>>4, tx=tid&15;
    float acc[8][8]={};
    for(int c0=0;c0<256;c0+=16){
        #pragma unroll
        for(int l=0;l<2;l++){
            int f4=tid+l*256;
            int kk=f4>>5, n4=(f4&31)<<2;
            *(float4*)&As[kk][n4] = *(const float4*)(x + ((size_t)b*CC + c0+kk)*NN + n0+n4);
            int oo=f4>>2, kc=(f4&3)<<2;
            int o=o0+oo;
            const float* wr = (o<64)? (Wq+(size_t)o*CC) : ((o<128)? (Wk+(size_t)(o-64)*CC) : (Wv+(size_t)(o-128)*CC));
            float4 w=*(const float4*)(wr + c0+kc);
            Bs[kc+0][oo]=w.x; Bs[kc+1][oo]=w.y; Bs[kc+2][oo]=w.z; Bs[kc+3][oo]=w.w;
        }
        __syncthreads();
        mma16(As,Bs,acc,ty,tx);
        __syncthreads();
    }
    float s = (ot==0)? 0.3535533905932738f : 1.0f;
    #pragma unroll
    for(int m=0;m<8;m++){
        int n=n0+ROWQ(ty,m);
        size_t base=((size_t)b*NN+n)*384 + o0;
        float4 v0={acc[m][0]*s,acc[m][1]*s,acc[m][2]*s,acc[m][3]*s};
        float4 v1={acc[m][4]*s,acc[m][5]*s,acc[m][6]*s,acc[m][7]*s};
        *(float4*)&g_qkv[base+tx*4]=v0;
        *(float4*)&g_qkv[base+64+tx*4]=v1;
    }
}

// ---------------- kernel 2: feature maps (q_p, k_p) and geo RFF (phi) -----------
__global__ __launch_bounds__(128) void feat_kernel(const float* __restrict__ pos,
    const float* __restrict__ P,  const float* __restrict__ Wg1, const float* __restrict__ bg1,
    const float* __restrict__ Wg2,const float* __restrict__ bg2, const float* __restrict__ logtau,
    const float* __restrict__ omega)
{
    __shared__ float Ps[4096];
    __shared__ float Om[256];
    __shared__ float sWg1[48], sbg1[16], sWg2[256], sbg2[16];
    int tid=threadIdx.x;
    for(int i=tid;i<4096;i+=128) Ps[i]=P[i];
    for(int i=tid;i<256;i+=128){ Om[i]=omega[i]; sWg2[i]=Wg2[i]; }
    if(tid<48) sWg1[tid]=Wg1[tid];
    if(tid<16){ sbg1[tid]=bg1[tid]; sbg2[tid]=bg2[tid]; }
    __syncthreads();

    int b=blockIdx.y;
    int n=blockIdx.x*128 + tid;
    size_t bn=(size_t)b*NN + n;

    float lt=logtau[0];
    float tau=log1pf(expf(lt)) + 1e-6f;
    float s2t=sqrtf(2.0f*tau);
    float p0=pos[bn*3+0], p1=pos[bn*3+1], p2=pos[bn*3+2];
    float g1[16], z[16];
    #pragma unroll
    for(int d=0;d<16;d++){
        float t=fmaf(sWg1[d*3],p0,fmaf(sWg1[d*3+1],p1,fmaf(sWg1[d*3+2],p2,sbg1[d])));
        g1[d]=fmaxf(t,0.0f);
    }
    float zn=0.0f;
    #pragma unroll
    for(int d=0;d<16;d++){
        float t=sbg2[d];
        #pragma unroll
        for(int e=0;e<16;e++) t=fmaf(sWg2[d*16+e],g1[e],t);
        z[d]=t*s2t;
        zn=fmaf(z[d],z[d],zn);
    }
    zn*=0.5f;
    #pragma unroll
    for(int r=0;r<16;r++){
        float t=0.0f;
        #pragma unroll
        for(int d=0;d<16;d++) t=fmaf(z[d],Om[d*16+r],t);
        g_phi[bn*16+r]=expf(t-zn)*0.25f;
    }

    const float* row = g_qkv + bn*384;
    const float fs = 0.08838834764831845f;
    for(int which=0;which<2;which++){
        const float* qr = row + which*64;
        float proj[64];
        #pragma unroll
        for(int m=0;m<64;m++) proj[m]=0.0f;
        for(int o=0;o<64;o++){
            float qo=qr[o];
            #pragma unroll
            for(int m=0;m<64;m++) proj[m]=fmaf(qo,Ps[o*64+m],proj[m]);
        }
        float M=0.0f;
        #pragma unroll
        for(int m=0;m<64;m++) M=fmaxf(M,fabsf(proj[m]));
        float* dst=(which==0? g_qp : g_kp) + bn*128;
        #pragma unroll
        for(int m=0;m<64;m++){
            dst[m]    = expf(proj[m]-M)*fs + 1e-6f;
            dst[64+m] = expf(-proj[m]-M)*fs + 1e-6f;
        }
    }
}

// ---------------- ksum: partial + reduce -----------------------------------------
__global__ __launch_bounds__(256) void ksum_part()
{
    __shared__ float skp[64][128];
    __shared__ float sph[64][16];
    int t=threadIdx.x;
    int ch=blockIdx.x, b=blockIdx.y;
    int nbase=ch*256;
    float acc[8]={};
    int iidx[8], jidx[8];
    #pragma unroll
    for(int k=0;k<8;k++){ int r=t+k*256; iidx[k]=r>>4; jidx[k]=r&15; }
    for(int sub=0;sub<4;sub++){
        int ns=nbase+sub*64;
        __syncthreads();
        #pragma unroll
        for(int l=0;l<8;l++){
            int f4=t+l*256; int row=f4>>5, c4=f4&31;
            *(float4*)&skp[row][c4*4]=*(const float4*)(g_kp+((size_t)b*NN+ns+row)*128+c4*4);
        }
        { int row=t>>2, c4=t&3;
          *(float4*)&sph[row][c4*4]=*(const float4*)(g_phi+((size_t)b*NN+ns+row)*16+c4*4); }
        __syncthreads();
        for(int n=0;n<64;n++){
            #pragma unroll
            for(int k=0;k<8;k++) acc[k]=fmaf(skp[n][iidx[k]],sph[n][jidx[k]],acc[k]);
        }
    }
    #pragma unroll
    for(int k=0;k<8;k++) g_kspart[((size_t)b*32+ch)*RR + t + k*256]=acc[k];
}

__global__ void ksum_reduce()
{
    int r=blockIdx.x*256+threadIdx.x; int b=blockIdx.y;
    float s=0.0f;
    #pragma unroll 8
    for(int c=0;c<32;c++) s+=g_kspart[((size_t)b*32+c)*RR + r];
    g_ksum[(size_t)b*RR + r]=s;
}

// ---------------- denom[b][n] = Phi_q[n]·k_sum + eps ------------------------------
__global__ __launch_bounds__(256) void denom_kernel()
{
    __shared__ float ks[2048];
    int b=blockIdx.y;
    for(int i=threadIdx.x;i<2048;i+=256) ks[i]=g_ksum[(size_t)b*RR+i];
    __syncthreads();
    int n=blockIdx.x*256 + threadIdx.x;
    size_t bn=(size_t)b*NN+n;
    float ph[16];
    #pragma unroll
    for(int r=0;r<16;r++) ph[r]=g_phi[bn*16+r];
    float d=0.0f;
    for(int i=0;i<128;i++){
        float t=0.0f;
        #pragma unroll
        for(int jj=0;jj<16;jj++) t=fmaf(ks[i*16+jj],ph[jj],t);
        d=fmaf(g_qp[bn*128+i],t,d);
    }
    g_denom[bn]=d+1e-6f;
}

// ================= tf32 mma GEMM 1: kv ===========================================
// kv[b][r][c] = sum_n (kp[n,i(r)]*phi[n,j(r)]) * v[n,c],  M=2048, N=256, K=8192
__global__ __launch_bounds__(256) void kv_tf32()
{
    __shared__ float As[32][136];   // [k][m]
    __shared__ float Bs[32][136];   // [k][c]
    const int mt=blockIdx.x, ct=blockIdx.y, b=blockIdx.z;
    const int tid=threadIdx.x, lane=tid&31, wid=tid>>5;
    const int wm=wid>>2, wn=wid&3;            // 2 x 4 warp grid
    const int m_base=wm*64, c_base=wn*32;
    const size_t bn=(size_t)b*NN;
    const int i0=mt*8;
    const float* vbase = g_qkv + bn*384 + 128 + (size_t)ct*128;
    const int skk=tid>>3, si=tid&7;           // A staging role

    float4 rB[4]; float rphi[16]; float rkp;
    {
        #pragma unroll
        for(int l=0;l<4;l++){ int f4=tid+l*256; int row=f4>>5, c4=(f4&31)<<2;
            rB[l]=*(const float4*)(vbase + (size_t)row*384 + c4); }
        const float* ph=g_phi + (bn+skk)*16;
        #pragma unroll
        for(int q=0;q<4;q++) *(float4*)(rphi+q*4)=*(const float4*)(ph+q*4);
        rkp = g_kp[(bn+skk)*128 + i0+si];
    }
    float acc[4][4][4];
    #pragma unroll
    for(int a=0;a<4;a++)
        #pragma unroll
        for(int bq=0;bq<4;bq++)
            #pragma unroll
            for(int cq=0;cq<4;cq++) acc[a][bq][cq]=0.0f;

    for(int it=0; it<256; ++it){
        __syncthreads();
        #pragma unroll
        for(int l=0;l<4;l++){ int f4=tid+l*256; int row=f4>>5, c4=(f4&31)<<2;
            *(float4*)&Bs[row][c4]=rB[l]; }
        {
            float av[16];
            #pragma unroll
            for(int j=0;j<16;j++) av[j]=rkp*rphi[j];
            #pragma unroll
            for(int q=0;q<4;q++) *(float4*)&As[skk][si*16+q*4]=*(float4*)(av+q*4);
        }
        __syncthreads();
        if(it+1<256){
            int n0=(it+1)*32;
            #pragma unroll
            for(int l=0;l<4;l++){ int f4=tid+l*256; int row=f4>>5, c4=(f4&31)<<2;
                rB[l]=*(const float4*)(vbase + (size_t)(n0+row)*384 + c4); }
            const float* ph=g_phi + (bn+n0+skk)*16;
            #pragma unroll
            for(int q=0;q<4;q++) *(float4*)(rphi+q*4)=*(const float4*)(ph+q*4);
            rkp = g_kp[(bn+n0+skk)*128 + i0+si];
        }
        #pragma unroll
        for(int ks=0;ks<32;ks+=8){
            uint32_t af[4][4], bf[4][2];
            const int kk=ks+(lane&3);
            #pragma unroll
            for(int mf=0;mf<4;mf++){
                int m0=m_base+mf*16+(lane>>2);
                af[mf][0]=f2tf32(As[kk][m0]);
                af[mf][1]=f2tf32(As[kk][m0+8]);
                af[mf][2]=f2tf32(As[kk+4][m0]);
                af[mf][3]=f2tf32(As[kk+4][m0+8]);
            }
            #pragma unroll
            for(int nf=0;nf<4;nf++){
                int c0=c_base+nf*8+(lane>>2);
                bf[nf][0]=f2tf32(Bs[kk][c0]);
                bf[nf][1]=f2tf32(Bs[kk+4][c0]);
            }
            #pragma unroll
            for(int mf=0;mf<4;mf++)
                #pragma unroll
                for(int nf=0;nf<4;nf++)
                    mma_tf32(acc[mf][nf],af[mf][0],af[mf][1],af[mf][2],af[mf][3],bf[nf][0],bf[nf][1]);
        }
    }
    #pragma unroll
    for(int mf=0;mf<4;mf++){
        int m = mt*128 + m_base + mf*16 + (lane>>2);
        #pragma unroll
        for(int nf=0;nf<4;nf++){
            int c = ct*128 + c_base + nf*8 + 2*(lane&3);
            float2 v0={acc[mf][nf][0],acc[mf][nf][1]};
            float2 v1={acc[mf][nf][2],acc[mf][nf][3]};
            *(float2*)&g_kv[((size_t)b*RR+m)*CC + c]   = v0;
            *(float2*)&g_kv[((size_t)b*RR+m+8)*CC + c] = v1;
        }
    }
}

// ================= tf32 mma GEMM 2: fsa ==========================================
// fsa[b][n][c] = (sum_r (qp[n,i(r)]*phi[n,j(r)]) * kv[r,c]) / denom[n]
// M=8192 (per b), N=256, K=2048
__global__ __launch_bounds__(256) void fsa_tf32()
{
    __shared__ float As[32][136];   // [k][m]
    __shared__ float Bs[32][136];   // [k][c]
    const int mt=blockIdx.x, ct=blockIdx.y, b=blockIdx.z;
    const int tid=threadIdx.x, lane=tid&31, wid=tid>>5;
    const int wm=wid>>2, wn=wid&3;
    const int m_base=wm*64, c_base=wn*32;
    const size_t bn0=(size_t)b*NN + (size_t)mt*128;
    const float* kvbase = g_kv + (size_t)b*RR*CC + (size_t)ct*128;
    const int sm=tid>>1, sip=tid&1;           // A staging role

    float rphi[16];
    {
        const float* ph=g_phi + (bn0+sm)*16;
        #pragma unroll
        for(int q=0;q<4;q++) *(float4*)(rphi+q*4)=*(const float4*)(ph+q*4);
    }
    float4 rB[4]; float rqp;
    {
        #pragma unroll
        for(int l=0;l<4;l++){ int f4=tid+l*256; int row=f4>>5, c4=(f4&31)<<2;
            rB[l]=*(const float4*)(kvbase + (size_t)row*CC + c4); }
        rqp = g_qp[(bn0+sm)*128 + sip];
    }
    float acc[4][4][4];
    #pragma unroll
    for(int a=0;a<4;a++)
        #pragma unroll
        for(int bq=0;bq<4;bq++)
            #pragma unroll
            for(int cq=0;cq<4;cq++) acc[a][bq][cq]=0.0f;

    for(int it=0; it<64; ++it){
        __syncthreads();
        #pragma unroll
        for(int l=0;l<4;l++){ int f4=tid+l*256; int row=f4>>5, c4=(f4&31)<<2;
            *(float4*)&Bs[row][c4]=rB[l]; }
        {
            #pragma unroll
            for(int j=0;j<16;j++) As[sip*16+j][sm]=rqp*rphi[j];
        }
        __syncthreads();
        if(it+1<64){
            int k0=(it+1)*32;
            #pragma unroll
            for(int l=0;l<4;l++){ int f4=tid+l*256; int row=f4>>5, c4=(f4&31)<<2;
                rB[l]=*(const float4*)(kvbase + (size_t)(k0+row)*CC + c4); }
            rqp = g_qp[(bn0+sm)*128 + (it+1)*2 + sip];
        }
        #pragma unroll
        for(int ks=0;ks<32;ks+=8){
            uint32_t af[4][4], bf[4][2];
            const int kk=ks+(lane&3);
            #pragma unroll
            for(int mf=0;mf<4;mf++){
                int m0=m_base+mf*16+(lane>>2);
                af[mf][0]=f2tf32(As[kk][m0]);
                af[mf][1]=f2tf32(As[kk][m0+8]);
                af[mf][2]=f2tf32(As[kk+4][m0]);
                af[mf][3]=f2tf32(As[kk+4][m0+8]);
            }
            #pragma unroll
            for(int nf=0;nf<4;nf++){
                int c0=c_base+nf*8+(lane>>2);
                bf[nf][0]=f2tf32(Bs[kk][c0]);
                bf[nf][1]=f2tf32(Bs[kk+4][c0]);
            }
            #pragma unroll
            for(int mf=0;mf<4;mf++)
                #pragma unroll
                for(int nf=0;nf<4;nf++)
                    mma_tf32(acc[mf][nf],af[mf][0],af[mf][1],af[mf][2],af[mf][3],bf[nf][0],bf[nf][1]);
        }
    }
    #pragma unroll
    for(int mf=0;mf<4;mf++){
        int ml = m_base + mf*16 + (lane>>2);
        float inv0 = 1.0f/g_denom[bn0+ml];
        float inv1 = 1.0f/g_denom[bn0+ml+8];
        #pragma unroll
        for(int nf=0;nf<4;nf++){
            int c = ct*128 + c_base + nf*8 + 2*(lane&3);
            float2 v0={acc[mf][nf][0]*inv0,acc[mf][nf][1]*inv0};
            float2 v1={acc[mf][nf][2]*inv1,acc[mf][nf][3]*inv1};
            *(float2*)&g_fsa[(bn0+ml)*CC + c]   = v0;
            *(float2*)&g_fsa[(bn0+ml+8)*CC + c] = v1;
        }
    }
}

// ---------------- h = Wp @ (x - fsa^T), + BN partial sums ------------------------
__global__ __launch_bounds__(256) void h_gemm(const float* __restrict__ x, const float* __restrict__ Wp)
{
    __shared__ float As[16][132];
    __shared__ float Bs[16][132];
    __shared__ float red[128][17];
    int ot=blockIdx.x, nt=blockIdx.y, b=blockIdx.z;
    int o0=ot*128, n0=nt*128;
    int tid=threadIdx.x, ty=tid>>4, tx=tid&15;
    float acc[8][8]={};
    for(int c0=0;c0<256;c0+=16){
        #pragma unroll
        for(int l=0;l<2;l++){
            int f4=tid+l*256;
            int oo=f4>>2, kc=(f4&3)<<2;
            float4 w=*(const float4*)(Wp + (size_t)(o0+oo)*256 + c0+kc);
            As[kc+0][oo]=w.x; As[kc+1][oo]=w.y; As[kc+2][oo]=w.z; As[kc+3][oo]=w.w;
            float4 f=*(const float4*)(g_fsa + ((size_t)b*NN + n0+oo)*256 + c0+kc);
            Bs[kc+0][oo]=-f.x; Bs[kc+1][oo]=-f.y; Bs[kc+2][oo]=-f.z; Bs[kc+3][oo]=-f.w;
        }
        __syncthreads();
        #pragma unroll
        for(int l=0;l<2;l++){
            int f4=tid+l*256;
            int kk=f4>>5, n4=(f4&31)<<2;
            float4 xv=*(const float4*)(x + ((size_t)b*CC + c0+kk)*NN + n0+n4);
            float4 cur=*(float4*)&Bs[kk][n4];
            cur.x+=xv.x; cur.y+=xv.y; cur.z+=xv.z; cur.w+=xv.w;
            *(float4*)&Bs[kk][n4]=cur;
        }
        __syncthreads();
        mma16(As,Bs,acc,ty,tx);
        __syncthreads();
    }
    #pragma unroll
    for(int m=0;m<8;m++){
        int o=o0+ROWQ(ty,m);
        size_t base=((size_t)b*CC+o)*NN + n0;
        float4 v0={acc[m][0],acc[m][1],acc[m][2],acc[m][3]};
        float4 v1={acc[m][4],acc[m][5],acc[m][6],acc[m][7]};
        *(float4*)&g_h[base+tx*4]=v0;
        *(float4*)&g_h[base+64+tx*4]=v1;
    }
    float s[8], s2[8];
    #pragma unroll
    for(int m=0;m<8;m++){
        float a=0.f,a2=0.f;
        #pragma unroll
        for(int n=0;n<8;n++){ a+=acc[m][n]; a2=fmaf(acc[m][n],acc[m][n],a2); }
        s[m]=a; s2[m]=a2;
    }
    #pragma unroll
    for(int m=0;m<8;m++) red[ROWQ(ty,m)][tx]=s[m];
    __syncthreads();
    if(tid<128){
        float t=0.f;
        #pragma unroll
        for(int k=0;k<16;k++) t+=red[tid][k];
        g_psum[((size_t)b*NTILES+nt)*CC + o0 + tid]=t;
    }
    __syncthreads();
    #pragma unroll
    for(int m=0;m<8;m++) red[ROWQ(ty,m)][tx]=s2[m];
    __syncthreads();
    if(tid<128){
        float t=0.f;
        #pragma unroll
        for(int k=0;k<16;k++) t+=red[tid][k];
        g_psumsq[((size_t)b*NTILES+nt)*CC + o0 + tid]=t;
    }
}

// ---------------- BN stats -> scale/bias ------------------------------------------
__global__ void stats_kernel(const float* __restrict__ gamma, const float* __restrict__ beta)
{
    int o=threadIdx.x;
    float s=0.f,s2=0.f;
    for(int t=0;t<BB*NTILES;t++){
        s +=g_psum  [(size_t)t*CC+o];
        s2+=g_psumsq[(size_t)t*CC+o];
    }
    const float inv=1.0f/(float)((size_t)BB*NN);
    float mean=s*inv;
    float var=s2*inv - mean*mean;
    float sc=gamma[o]*rsqrtf(var+1e-5f);
    g_scale[o]=sc;
    g_bias[o]=beta[o]-mean*sc;
}

// ---------------- out = relu(BN(h)) + x --------------------------------------------
__global__ __launch_bounds__(256) void final_kernel(const float* __restrict__ x, float* __restrict__ out)
{
    size_t i4=(size_t)blockIdx.x*256 + threadIdx.x;
    size_t f=i4*4;
    int c=(int)((f/NN)%CC);
    float sc=g_scale[c], bi=g_bias[c];
    float4 h=*(const float4*)(g_h+f);
    float4 xv=*(const float4*)(x+f);
    float4 o;
    o.x=fmaxf(fmaf(h.x,sc,bi),0.0f)+xv.x;
    o.y=fmaxf(fmaf(h.y,sc,bi),0.0f)+xv.y;
    o.z=fmaxf(fmaf(h.z,sc,bi),0.0f)+xv.z;
    o.w=fmaxf(fmaf(h.w,sc,bi),0.0f)+xv.w;
    *(float4*)(out+f)=o;
}

// ---------------- launch ------------------------------------------------------------
extern "C" void kernel_launch(void* const* d_in, const int* in_sizes, int n_in,
                              void* d_out, int out_size)
{
    const float* x      =(const float*)d_in[0];
    const float* pos    =(const float*)d_in[1];
    const float* Wq     =(const float*)d_in[2];
    const float* Wk     =(const float*)d_in[3];
    const float* Wv     =(const float*)d_in[4];
    const float* proj_sm=(const float*)d_in[5];
    const float* Wg1    =(const float*)d_in[6];
    const float* bg1    =(const float*)d_in[7];
    const float* Wg2    =(const float*)d_in[8];
    const float* bg2    =(const float*)d_in[9];
    const float* log_tau=(const float*)d_in[10];
    const float* omega  =(const float*)d_in[11];
    const float* Wp     =(const float*)d_in[12];
    const float* gamma  =(const float*)d_in[13];
    const float* beta   =(const float*)d_in[14];
    float* out=(float*)d_out;

    qkv_gemm    <<<dim3(64,3,BB),256>>>(x,Wq,Wk,Wv);
    feat_kernel <<<dim3(64,BB),128>>>(pos,proj_sm,Wg1,bg1,Wg2,bg2,log_tau,omega);
    ksum_part   <<<dim3(32,BB),256>>>();
    ksum_reduce <<<dim3(8,BB),256>>>();
    kv_tf32     <<<dim3(16,2,BB),256>>>();
    denom_kernel<<<dim3(32,BB),256>>>();
    fsa_tf32    <<<dim3(64,2,BB),256>>>();
    h_gemm      <<<dim3(2,64,BB),256>>>(x,Wp);
    stats_kernel<<<1,256>>>(gamma,beta);
    final_kernel<<<8192,256>>>(x,out);
}

// round 4
// speedup vs baseline: 2.1967x; 1.2118x over previous
#include <cuda_runtime.h>
#include <math.h>
#include <stdint.h>

#define BB 4
#define CC 256
#define NN 8192
#define RSM 128
#define RG 16
#define RR 2048       // RSM*RG
#define NTILES 64     // NN/128

// ---------------- scratch (static device globals; no allocation) ----------------
__device__ float g_qk [(size_t)BB*NN*128];     // [b][n][0:64 q,64:128 k]
__device__ float g_v  [(size_t)BB*NN*256];     // [b][n][c]
__device__ float g_qp [(size_t)BB*NN*RSM];
__device__ float g_kp [(size_t)BB*NN*RSM];
__device__ float g_phi[(size_t)BB*NN*RG];
__device__ float g_kv [(size_t)BB*RR*CC];
__device__ float g_ksum[(size_t)BB*RR];
__device__ float g_kspart[(size_t)BB*32*RR];
__device__ float g_denom[(size_t)BB*NN];
__device__ float g_fsa[(size_t)BB*NN*CC];
__device__ float g_h  [(size_t)BB*CC*NN];
__device__ float g_psum  [(size_t)BB*NTILES*CC];
__device__ float g_psumsq[(size_t)BB*NTILES*CC];
__device__ float g_scale[CC];
__device__ float g_bias [CC];

#define ROWQ(g,m) (((m)<4) ? ((g)*4+(m)) : (64+(g)*4+((m)-4)))

// ================= tf32 warp-MMA helpers =========================================
__device__ __forceinline__ uint32_t f2tf32(float f){
    uint32_t r; asm("cvt.rna.tf32.f32 %0, %1;" : "=r"(r) : "f"(f)); return r;
}
__device__ __forceinline__ void mma_tf32(float* c,
    uint32_t a0, uint32_t a1, uint32_t a2, uint32_t a3, uint32_t b0, uint32_t b1){
    asm volatile(
      "mma.sync.aligned.m16n8k8.row.col.f32.tf32.tf32.f32 "
      "{%0,%1,%2,%3},{%4,%5,%6,%7},{%8,%9},{%0,%1,%2,%3};"
      : "+f"(c[0]),"+f"(c[1]),"+f"(c[2]),"+f"(c[3])
      : "r"(a0),"r"(a1),"r"(a2),"r"(a3),"r"(b0),"r"(b1));
}

// MMA inner phase over a 32-deep K chunk held pre-converted in SMEM.
__device__ __forceinline__ void mma_chunk(const uint32_t (*As)[136], const uint32_t (*Bs)[136],
                                          float acc[4][4][4], int m_base, int c_base, int lane){
    #pragma unroll
    for(int ks=0;ks<32;ks+=8){
        uint32_t af[4][4], bf[4][2];
        const int kk=ks+(lane&3);
        #pragma unroll
        for(int mf=0;mf<4;mf++){
            int m0=m_base+mf*16+(lane>>2);
            af[mf][0]=As[kk][m0];
            af[mf][1]=As[kk][m0+8];
            af[mf][2]=As[kk+4][m0];
            af[mf][3]=As[kk+4][m0+8];
        }
        #pragma unroll
        for(int nf=0;nf<4;nf++){
            int c0=c_base+nf*8+(lane>>2);
            bf[nf][0]=Bs[kk][c0];
            bf[nf][1]=Bs[kk+4][c0];
        }
        #pragma unroll
        for(int mf=0;mf<4;mf++)
            #pragma unroll
            for(int nf=0;nf<4;nf++)
                mma_tf32(acc[mf][nf],af[mf][0],af[mf][1],af[mf][2],af[mf][3],bf[nf][0],bf[nf][1]);
    }
}

// =========================== FFMA helper =========================================
__device__ __forceinline__ void mma16(const float (*As)[132], const float (*Bs)[132],
                                      float acc[8][8], int ty, int tx){
    #pragma unroll
    for(int kk=0;kk<16;kk++){
        float a[8], bv[8];
        *(float4*)(a)    = *(const float4*)&As[kk][ty*4];
        *(float4*)(a+4)  = *(const float4*)&As[kk][64+ty*4];
        *(float4*)(bv)   = *(const float4*)&Bs[kk][tx*4];
        *(float4*)(bv+4) = *(const float4*)&Bs[kk][64+tx*4];
        #pragma unroll
        for(int m=0;m<8;m++)
            #pragma unroll
            for(int n=0;n<8;n++)
                acc[m][n]=fmaf(a[m],bv[n],acc[m][n]);
    }
}

// ---------------- kernel: QK = X^T @ [Wq;Wk]^T (scaled), fp32 --------------------
__global__ __launch_bounds__(256) void qk_gemm(const float* __restrict__ x,
    const float* __restrict__ Wq, const float* __restrict__ Wk)
{
    __shared__ float As[16][132];
    __shared__ float Bs[16][132];
    int nt=blockIdx.x, b=blockIdx.y;
    int n0=nt*128;
    int tid=threadIdx.x, ty=tid>>4, tx=tid&15;
    float acc[8][8]={};
    for(int c0=0;c0<256;c0+=16){
        #pragma unroll
        for(int l=0;l<2;l++){
            int f4=tid+l*256;
            int kk=f4>>5, n4=(f4&31)<<2;
            *(float4*)&As[kk][n4] = *(const float4*)(x + ((size_t)b*CC + c0+kk)*NN + n0+n4);
            int oo=f4>>2, kc=(f4&3)<<2;
            const float* wr = (oo<64)? (Wq+(size_t)oo*CC) : (Wk+(size_t)(oo-64)*CC);
            float4 w=*(const float4*)(wr + c0+kc);
            Bs[kc+0][oo]=w.x; Bs[kc+1][oo]=w.y; Bs[kc+2][oo]=w.z; Bs[kc+3][oo]=w.w;
        }
        __syncthreads();
        mma16(As,Bs,acc,ty,tx);
        __syncthreads();
    }
    const float s = 0.3535533905932738f;   // 64^-0.25
    #pragma unroll
    for(int m=0;m<8;m++){
        int n=n0+ROWQ(ty,m);
        size_t base=((size_t)b*NN+n)*128;
        float4 v0={acc[m][0]*s,acc[m][1]*s,acc[m][2]*s,acc[m][3]*s};
        float4 v1={acc[m][4]*s,acc[m][5]*s,acc[m][6]*s,acc[m][7]*s};
        *(float4*)&g_qk[base+tx*4]=v0;
        *(float4*)&g_qk[base+64+tx*4]=v1;
    }
}

// ---------------- kernel: V = X^T @ Wv^T (tf32 mma) ------------------------------
__global__ __launch_bounds__(256) void v_tf32(const float* __restrict__ x, const float* __restrict__ Wv)
{
    __shared__ uint32_t As[32][136];   // [k=c][n]
    __shared__ uint32_t Bs[32][136];   // [k=c][o]
    const int nt=blockIdx.x, ct=blockIdx.y, b=blockIdx.z;
    const int tid=threadIdx.x, lane=tid&31, wid=tid>>5;
    const int m_base=(wid>>2)*64, c_base=(wid&3)*32;
    const int n0=nt*128;

    float4 rA[4], rW[4];
    #pragma unroll
    for(int l=0;l<4;l++){
        int f4=tid+l*256;
        int kk=f4>>5, n4=(f4&31)<<2;
        rA[l]=*(const float4*)(x + ((size_t)b*CC + kk)*NN + n0+n4);
        int oo=f4>>3, kc4=(f4&7)<<2;
        rW[l]=*(const float4*)(Wv + (size_t)(ct*128+oo)*CC + kc4);
    }
    float acc[4][4][4];
    #pragma unroll
    for(int a=0;a<4;a++)
        #pragma unroll
        for(int bq=0;bq<4;bq++)
            #pragma unroll
            for(int cq=0;cq<4;cq++) acc[a][bq][cq]=0.0f;

    for(int it=0; it<8; ++it){
        __syncthreads();
        #pragma unroll
        for(int l=0;l<4;l++){
            int f4=tid+l*256;
            int kk=f4>>5, n4=(f4&31)<<2;
            uint4 u={f2tf32(rA[l].x),f2tf32(rA[l].y),f2tf32(rA[l].z),f2tf32(rA[l].w)};
            *(uint4*)&As[kk][n4]=u;
            int oo=f4>>3, kc=(f4&7)<<2;
            Bs[kc+0][oo]=f2tf32(rW[l].x); Bs[kc+1][oo]=f2tf32(rW[l].y);
            Bs[kc+2][oo]=f2tf32(rW[l].z); Bs[kc+3][oo]=f2tf32(rW[l].w);
        }
        __syncthreads();
        if(it+1<8){
            int c0=(it+1)*32;
            #pragma unroll
            for(int l=0;l<4;l++){
                int f4=tid+l*256;
                int kk=f4>>5, n4=(f4&31)<<2;
                rA[l]=*(const float4*)(x + ((size_t)b*CC + c0+kk)*NN + n0+n4);
                int oo=f4>>3, kc4=(f4&7)<<2;
                rW[l]=*(const float4*)(Wv + (size_t)(ct*128+oo)*CC + c0+kc4);
            }
        }
        mma_chunk(As,Bs,acc,m_base,c_base,lane);
    }
    #pragma unroll
    for(int mf=0;mf<4;mf++){
        int m = m_base + mf*16 + (lane>>2);
        #pragma unroll
        for(int nf=0;nf<4;nf++){
            int c = ct*128 + c_base + nf*8 + 2*(lane&3);
            float2 v0={acc[mf][nf][0],acc[mf][nf][1]};
            float2 v1={acc[mf][nf][2],acc[mf][nf][3]};
            *(float2*)&g_v[((size_t)b*NN + n0+m)*256 + c]   = v0;
            *(float2*)&g_v[((size_t)b*NN + n0+m+8)*256 + c] = v1;
        }
    }
}

// ---------------- feature maps (q_p, k_p) and geo RFF (phi) ----------------------
__global__ __launch_bounds__(128) void feat_kernel(const float* __restrict__ pos,
    const float* __restrict__ P,  const float* __restrict__ Wg1, const float* __restrict__ bg1,
    const float* __restrict__ Wg2,const float* __restrict__ bg2, const float* __restrict__ logtau,
    const float* __restrict__ omega)
{
    __shared__ float Ps[4096];
    __shared__ float Om[256];
    __shared__ float sWg1[48], sbg1[16], sWg2[256], sbg2[16];
    int tid=threadIdx.x;
    for(int i=tid;i<4096;i+=128) Ps[i]=P[i];
    for(int i=tid;i<256;i+=128){ Om[i]=omega[i]; sWg2[i]=Wg2[i]; }
    if(tid<48) sWg1[tid]=Wg1[tid];
    if(tid<16){ sbg1[tid]=bg1[tid]; sbg2[tid]=bg2[tid]; }
    __syncthreads();

    int b=blockIdx.y;
    int n=blockIdx.x*128 + tid;
    size_t bn=(size_t)b*NN + n;

    float lt=logtau[0];
    float tau=log1pf(expf(lt)) + 1e-6f;
    float s2t=sqrtf(2.0f*tau);
    float p0=pos[bn*3+0], p1=pos[bn*3+1], p2=pos[bn*3+2];
    float g1[16], z[16];
    #pragma unroll
    for(int d=0;d<16;d++){
        float t=fmaf(sWg1[d*3],p0,fmaf(sWg1[d*3+1],p1,fmaf(sWg1[d*3+2],p2,sbg1[d])));
        g1[d]=fmaxf(t,0.0f);
    }
    float zn=0.0f;
    #pragma unroll
    for(int d=0;d<16;d++){
        float t=sbg2[d];
        #pragma unroll
        for(int e=0;e<16;e++) t=fmaf(sWg2[d*16+e],g1[e],t);
        z[d]=t*s2t;
        zn=fmaf(z[d],z[d],zn);
    }
    zn*=0.5f;
    #pragma unroll
    for(int r=0;r<16;r++){
        float t=0.0f;
        #pragma unroll
        for(int d=0;d<16;d++) t=fmaf(z[d],Om[d*16+r],t);
        g_phi[bn*16+r]=expf(t-zn)*0.25f;
    }

    const float* row = g_qk + bn*128;
    const float fs = 0.08838834764831845f;
    for(int which=0;which<2;which++){
        const float* qr = row + which*64;
        float proj[64];
        #pragma unroll
        for(int m=0;m<64;m++) proj[m]=0.0f;
        for(int o=0;o<64;o++){
            float qo=qr[o];
            #pragma unroll
            for(int m=0;m<64;m++) proj[m]=fmaf(qo,Ps[o*64+m],proj[m]);
        }
        float M=0.0f;
        #pragma unroll
        for(int m=0;m<64;m++) M=fmaxf(M,fabsf(proj[m]));
        float* dst=(which==0? g_qp : g_kp) + bn*128;
        #pragma unroll
        for(int m=0;m<64;m++){
            dst[m]    = expf(proj[m]-M)*fs + 1e-6f;
            dst[64+m] = expf(-proj[m]-M)*fs + 1e-6f;
        }
    }
}

// ---------------- ksum: partial + reduce -----------------------------------------
__global__ __launch_bounds__(256) void ksum_part()
{
    __shared__ float skp[64][128];
    __shared__ float sph[64][16];
    int t=threadIdx.x;
    int ch=blockIdx.x, b=blockIdx.y;
    int nbase=ch*256;
    float acc[8]={};
    int iidx[8], jidx[8];
    #pragma unroll
    for(int k=0;k<8;k++){ int r=t+k*256; iidx[k]=r>>4; jidx[k]=r&15; }
    for(int sub=0;sub<4;sub++){
        int ns=nbase+sub*64;
        __syncthreads();
        #pragma unroll
        for(int l=0;l<8;l++){
            int f4=t+l*256; int row=f4>>5, c4=f4&31;
            *(float4*)&skp[row][c4*4]=*(const float4*)(g_kp+((size_t)b*NN+ns+row)*128+c4*4);
        }
        { int row=t>>2, c4=t&3;
          *(float4*)&sph[row][c4*4]=*(const float4*)(g_phi+((size_t)b*NN+ns+row)*16+c4*4); }
        __syncthreads();
        for(int n=0;n<64;n++){
            #pragma unroll
            for(int k=0;k<8;k++) acc[k]=fmaf(skp[n][iidx[k]],sph[n][jidx[k]],acc[k]);
        }
    }
    #pragma unroll
    for(int k=0;k<8;k++) g_kspart[((size_t)b*32+ch)*RR + t + k*256]=acc[k];
}

__global__ void ksum_reduce()
{
    int r=blockIdx.x*256+threadIdx.x; int b=blockIdx.y;
    float s=0.0f;
    #pragma unroll 8
    for(int c=0;c<32;c++) s+=g_kspart[((size_t)b*32+c)*RR + r];
    g_ksum[(size_t)b*RR + r]=s;
}

// ---------------- denom[b][n] = Phi_q[n]·k_sum + eps ------------------------------
__global__ __launch_bounds__(256) void denom_kernel()
{
    __shared__ float ks[2048];
    int b=blockIdx.y;
    for(int i=threadIdx.x;i<2048;i+=256) ks[i]=g_ksum[(size_t)b*RR+i];
    __syncthreads();
    int n=blockIdx.x*256 + threadIdx.x;
    size_t bn=(size_t)b*NN+n;
    float ph[16];
    #pragma unroll
    for(int r=0;r<16;r++) ph[r]=g_phi[bn*16+r];
    float d=0.0f;
    for(int i=0;i<128;i++){
        float t=0.0f;
        #pragma unroll
        for(int jj=0;jj<16;jj++) t=fmaf(ks[i*16+jj],ph[jj],t);
        d=fmaf(g_qp[bn*128+i],t,d);
    }
    g_denom[bn]=d+1e-6f;
}

// ================= tf32 mma GEMM 1: kv ===========================================
// kv[b][r][c] = sum_n (kp[n,i(r)]*phi[n,j(r)]) * v[n,c],  M=2048, N=256, K=8192
__global__ __launch_bounds__(256) void kv_tf32()
{
    __shared__ uint32_t As[32][136];   // [k][m] tf32
    __shared__ uint32_t Bs[32][136];   // [k][c] tf32
    const int mt=blockIdx.x, ct=blockIdx.y, b=blockIdx.z;
    const int tid=threadIdx.x, lane=tid&31, wid=tid>>5;
    const int m_base=(wid>>2)*64, c_base=(wid&3)*32;
    const size_t bn=(size_t)b*NN;
    const int i0=mt*8;
    const float* vbase = g_v + bn*256 + (size_t)ct*128;
    const int skk=tid>>3, si=tid&7;

    float4 rB[4]; float rphi[16]; float rkp;
    {
        #pragma unroll
        for(int l=0;l<4;l++){ int f4=tid+l*256; int row=f4>>5, c4=(f4&31)<<2;
            rB[l]=*(const float4*)(vbase + (size_t)row*256 + c4); }
        const float* ph=g_phi + (bn+skk)*16;
        #pragma unroll
        for(int q=0;q<4;q++) *(float4*)(rphi+q*4)=*(const float4*)(ph+q*4);
        rkp = g_kp[(bn+skk)*128 + i0+si];
    }
    float acc[4][4][4];
    #pragma unroll
    for(int a=0;a<4;a++)
        #pragma unroll
        for(int bq=0;bq<4;bq++)
            #pragma unroll
            for(int cq=0;cq<4;cq++) acc[a][bq][cq]=0.0f;

    for(int it=0; it<256; ++it){
        __syncthreads();
        #pragma unroll
        for(int l=0;l<4;l++){ int f4=tid+l*256; int row=f4>>5, c4=(f4&31)<<2;
            uint4 u={f2tf32(rB[l].x),f2tf32(rB[l].y),f2tf32(rB[l].z),f2tf32(rB[l].w)};
            *(uint4*)&Bs[row][c4]=u; }
        {
            uint32_t av[16];
            #pragma unroll
            for(int j=0;j<16;j++) av[j]=f2tf32(rkp*rphi[j]);
            #pragma unroll
            for(int q=0;q<4;q++) *(uint4*)&As[skk][si*16+q*4]=*(uint4*)(av+q*4);
        }
        __syncthreads();
        if(it+1<256){
            int n0=(it+1)*32;
            #pragma unroll
            for(int l=0;l<4;l++){ int f4=tid+l*256; int row=f4>>5, c4=(f4&31)<<2;
                rB[l]=*(const float4*)(vbase + (size_t)(n0+row)*256 + c4); }
            const float* ph=g_phi + (bn+n0+skk)*16;
            #pragma unroll
            for(int q=0;q<4;q++) *(float4*)(rphi+q*4)=*(const float4*)(ph+q*4);
            rkp = g_kp[(bn+n0+skk)*128 + i0+si];
        }
        mma_chunk(As,Bs,acc,m_base,c_base,lane);
    }
    #pragma unroll
    for(int mf=0;mf<4;mf++){
        int m = mt*128 + m_base + mf*16 + (lane>>2);
        #pragma unroll
        for(int nf=0;nf<4;nf++){
            int c = ct*128 + c_base + nf*8 + 2*(lane&3);
            float2 v0={acc[mf][nf][0],acc[mf][nf][1]};
            float2 v1={acc[mf][nf][2],acc[mf][nf][3]};
            *(float2*)&g_kv[((size_t)b*RR+m)*CC + c]   = v0;
            *(float2*)&g_kv[((size_t)b*RR+m+8)*CC + c] = v1;
        }
    }
}

// ================= tf32 mma GEMM 2: fsa ==========================================
// fsa[b][n][c] = (sum_r (qp[n,i(r)]*phi[n,j(r)]) * kv[r,c]) / denom[n]
__global__ __launch_bounds__(256) void fsa_tf32()
{
    __shared__ uint32_t As[32][136];   // [k][m] tf32
    __shared__ uint32_t Bs[32][136];   // [k][c] tf32
    const int mt=blockIdx.x, ct=blockIdx.y, b=blockIdx.z;
    const int tid=threadIdx.x, lane=tid&31, wid=tid>>5;
    const int m_base=(wid>>2)*64, c_base=(wid&3)*32;
    const size_t bn0=(size_t)b*NN + (size_t)mt*128;
    const float* kvbase = g_kv + (size_t)b*RR*CC + (size_t)ct*128;
    const int sm=tid>>1, sip=tid&1;

    float rphi[16];
    {
        const float* ph=g_phi + (bn0+sm)*16;
        #pragma unroll
        for(int q=0;q<4;q++) *(float4*)(rphi+q*4)=*(const float4*)(ph+q*4);
    }
    float4 rB[4]; float rqp;
    {
        #pragma unroll
        for(int l=0;l<4;l++){ int f4=tid+l*256; int row=f4>>5, c4=(f4&31)<<2;
            rB[l]=*(const float4*)(kvbase + (size_t)row*CC + c4); }
        rqp = g_qp[(bn0+sm)*128 + sip];
    }
    float acc[4][4][4];
    #pragma unroll
    for(int a=0;a<4;a++)
        #pragma unroll
        for(int bq=0;bq<4;bq++)
            #pragma unroll
            for(int cq=0;cq<4;cq++) acc[a][bq][cq]=0.0f;

    for(int it=0; it<64; ++it){
        __syncthreads();
        #pragma unroll
        for(int l=0;l<4;l++){ int f4=tid+l*256; int row=f4>>5, c4=(f4&31)<<2;
            uint4 u={f2tf32(rB[l].x),f2tf32(rB[l].y),f2tf32(rB[l].z),f2tf32(rB[l].w)};
            *(uint4*)&Bs[row][c4]=u; }
        {
            #pragma unroll
            for(int j=0;j<16;j++) As[sip*16+j][sm]=f2tf32(rqp*rphi[j]);
        }
        __syncthreads();
        if(it+1<64){
            int k0=(it+1)*32;
            #pragma unroll
            for(int l=0;l<4;l++){ int f4=tid+l*256; int row=f4>>5, c4=(f4&31)<<2;
                rB[l]=*(const float4*)(kvbase + (size_t)(k0+row)*CC + c4); }
            rqp = g_qp[(bn0+sm)*128 + (it+1)*2 + sip];
        }
        mma_chunk(As,Bs,acc,m_base,c_base,lane);
    }
    #pragma unroll
    for(int mf=0;mf<4;mf++){
        int ml = m_base + mf*16 + (lane>>2);
        float inv0 = 1.0f/g_denom[bn0+ml];
        float inv1 = 1.0f/g_denom[bn0+ml+8];
        #pragma unroll
        for(int nf=0;nf<4;nf++){
            int c = ct*128 + c_base + nf*8 + 2*(lane&3);
            float2 v0={acc[mf][nf][0]*inv0,acc[mf][nf][1]*inv0};
            float2 v1={acc[mf][nf][2]*inv1,acc[mf][nf][3]*inv1};
            *(float2*)&g_fsa[(bn0+ml)*CC + c]   = v0;
            *(float2*)&g_fsa[(bn0+ml+8)*CC + c] = v1;
        }
    }
}

// ---------------- h = Wp @ (x - fsa^T) (tf32 mma) + BN partials -------------------
__global__ __launch_bounds__(256) void h_tf32(const float* __restrict__ x, const float* __restrict__ Wp)
{
    __shared__ uint32_t As[32][136];   // [k=c][o] tf32 Wp
    __shared__ uint32_t Bs[32][136];   // [k=c][n] tf32 (x - fsa)
    __shared__ float red[128][5];
    const int mt=blockIdx.x, nt=blockIdx.y, b=blockIdx.z;
    const int o0=mt*128, n0=nt*128;
    const int tid=threadIdx.x, lane=tid&31, wid=tid>>5;
    const int m_base=(wid>>2)*64, c_base=(wid&3)*32;

    float4 rW[4], rF[4], rX[4];
    #pragma unroll
    for(int l=0;l<4;l++){
        int f4=tid+l*256;
        int oo=f4>>3, kc4=(f4&7)<<2;
        rW[l]=*(const float4*)(Wp + (size_t)(o0+oo)*CC + kc4);
        rF[l]=*(const float4*)(g_fsa + ((size_t)b*NN+n0+oo)*CC + kc4);
        int kk=f4>>5, n4=(f4&31)<<2;
        rX[l]=*(const float4*)(x + ((size_t)b*CC+kk)*NN + n0+n4);
    }
    float acc[4][4][4];
    #pragma unroll
    for(int a=0;a<4;a++)
        #pragma unroll
        for(int bq=0;bq<4;bq++)
            #pragma unroll
            for(int cq=0;cq<4;cq++) acc[a][bq][cq]=0.0f;

    for(int it=0; it<8; ++it){
        __syncthreads();
        #pragma unroll
        for(int l=0;l<4;l++){
            int f4=tid+l*256;
            int oo=f4>>3, kc=(f4&7)<<2;
            As[kc+0][oo]=f2tf32(rW[l].x); As[kc+1][oo]=f2tf32(rW[l].y);
            As[kc+2][oo]=f2tf32(rW[l].z); As[kc+3][oo]=f2tf32(rW[l].w);
            Bs[kc+0][oo]=__float_as_uint(-rF[l].x); Bs[kc+1][oo]=__float_as_uint(-rF[l].y);
            Bs[kc+2][oo]=__float_as_uint(-rF[l].z); Bs[kc+3][oo]=__float_as_uint(-rF[l].w);
        }
        __syncthreads();
        #pragma unroll
        for(int l=0;l<4;l++){
            int f4=tid+l*256;
            int kk=f4>>5, n4=(f4&31)<<2;
            uint4 cur=*(uint4*)&Bs[kk][n4];
            cur.x=f2tf32(__uint_as_float(cur.x)+rX[l].x);
            cur.y=f2tf32(__uint_as_float(cur.y)+rX[l].y);
            cur.z=f2tf32(__uint_as_float(cur.z)+rX[l].z);
            cur.w=f2tf32(__uint_as_float(cur.w)+rX[l].w);
            *(uint4*)&Bs[kk][n4]=cur;
        }
        __syncthreads();
        if(it+1<8){
            int c0=(it+1)*32;
            #pragma unroll
            for(int l=0;l<4;l++){
                int f4=tid+l*256;
                int oo=f4>>3, kc4=(f4&7)<<2;
                rW[l]=*(const float4*)(Wp + (size_t)(o0+oo)*CC + c0+kc4);
                rF[l]=*(const float4*)(g_fsa + ((size_t)b*NN+n0+oo)*CC + c0+kc4);
                int kk=f4>>5, n4=(f4&31)<<2;
                rX[l]=*(const float4*)(x + ((size_t)b*CC+c0+kk)*NN + n0+n4);
            }
        }
        mma_chunk(As,Bs,acc,m_base,c_base,lane);
    }
    // store h
    #pragma unroll
    for(int mf=0;mf<4;mf++){
        int r0 = m_base + mf*16 + (lane>>2);
        #pragma unroll
        for(int nf=0;nf<4;nf++){
            int nl = c_base + nf*8 + 2*(lane&3);
            float2 v0={acc[mf][nf][0],acc[mf][nf][1]};
            float2 v1={acc[mf][nf][2],acc[mf][nf][3]};
            *(float2*)&g_h[((size_t)b*CC + o0+r0)*NN + n0+nl]   = v0;
            *(float2*)&g_h[((size_t)b*CC + o0+r0+8)*NN + n0+nl] = v1;
        }
    }
    // BN partials (deterministic): per-o sums over this block's 128 n
    float s[4][2], q2[4][2];
    #pragma unroll
    for(int mf=0;mf<4;mf++){
        float a0=0.f,a1=0.f,b0=0.f,b1=0.f;
        #pragma unroll
        for(int nf=0;nf<4;nf++){
            a0+=acc[mf][nf][0]+acc[mf][nf][1];
            b0+=acc[mf][nf][0]*acc[mf][nf][0]+acc[mf][nf][1]*acc[mf][nf][1];
            a1+=acc[mf][nf][2]+acc[mf][nf][3];
            b1+=acc[mf][nf][2]*acc[mf][nf][2]+acc[mf][nf][3]*acc[mf][nf][3];
        }
        s[mf][0]=a0; s[mf][1]=a1; q2[mf][0]=b0; q2[mf][1]=b1;
    }
    #pragma unroll
    for(int mf=0;mf<4;mf++)
        #pragma unroll
        for(int hh=0;hh<2;hh++){
            s[mf][hh]  += __shfl_xor_sync(0xffffffff, s[mf][hh], 1);
            s[mf][hh]  += __shfl_xor_sync(0xffffffff, s[mf][hh], 2);
            q2[mf][hh] += __shfl_xor_sync(0xffffffff, q2[mf][hh], 1);
            q2[mf][hh] += __shfl_xor_sync(0xffffffff, q2[mf][hh], 2);
        }
    __syncthreads();
    if((lane&3)==0){
        #pragma unroll
        for(int mf=0;mf<4;mf++)
            #pragma unroll
            for(int hh=0;hh<2;hh++)
                red[m_base+mf*16+(lane>>2)+hh*8][wid&3]=s[mf][hh];
    }
    __syncthreads();
    if(tid<128){
        float t=red[tid][0]+red[tid][1]+red[tid][2]+red[tid][3];
        g_psum[((size_t)b*NTILES+nt)*CC + o0 + tid]=t;
    }
    __syncthreads();
    if((lane&3)==0){
        #pragma unroll
        for(int mf=0;mf<4;mf++)
            #pragma unroll
            for(int hh=0;hh<2;hh++)
                red[m_base+mf*16+(lane>>2)+hh*8][wid&3]=q2[mf][hh];
    }
    __syncthreads();
    if(tid<128){
        float t=red[tid][0]+red[tid][1]+red[tid][2]+red[tid][3];
        g_psumsq[((size_t)b*NTILES+nt)*CC + o0 + tid]=t;
    }
}

// ---------------- BN stats -> scale/bias ------------------------------------------
__global__ void stats_kernel(const float* __restrict__ gamma, const float* __restrict__ beta)
{
    int o=threadIdx.x;
    float s=0.f,s2=0.f;
    for(int t=0;t<BB*NTILES;t++){
        s +=g_psum  [(size_t)t*CC+o];
        s2+=g_psumsq[(size_t)t*CC+o];
    }
    const float inv=1.0f/(float)((size_t)BB*NN);
    float mean=s*inv;
    float var=s2*inv - mean*mean;
    float sc=gamma[o]*rsqrtf(var+1e-5f);
    g_scale[o]=sc;
    g_bias[o]=beta[o]-mean*sc;
}

// ---------------- out = relu(BN(h)) + x --------------------------------------------
__global__ __launch_bounds__(256) void final_kernel(const float* __restrict__ x, float* __restrict__ out)
{
    size_t i4=(size_t)blockIdx.x*256 + threadIdx.x;
    size_t f=i4*4;
    int c=(int)((f/NN)%CC);
    float sc=g_scale[c], bi=g_bias[c];
    float4 h=*(const float4*)(g_h+f);
    float4 xv=*(const float4*)(x+f);
    float4 o;
    o.x=fmaxf(fmaf(h.x,sc,bi),0.0f)+xv.x;
    o.y=fmaxf(fmaf(h.y,sc,bi),0.0f)+xv.y;
    o.z=fmaxf(fmaf(h.z,sc,bi),0.0f)+xv.z;
    o.w=fmaxf(fmaf(h.w,sc,bi),0.0f)+xv.w;
    *(float4*)(out+f)=o;
}

// ---------------- launch ------------------------------------------------------------
extern "C" void kernel_launch(void* const* d_in, const int* in_sizes, int n_in,
                              void* d_out, int out_size)
{
    const float* x      =(const float*)d_in[0];
    const float* pos    =(const float*)d_in[1];
    const float* Wq     =(const float*)d_in[2];
    const float* Wk     =(const float*)d_in[3];
    const float* Wv     =(const float*)d_in[4];
    const float* proj_sm=(const float*)d_in[5];
    const float* Wg1    =(const float*)d_in[6];
    const float* bg1    =(const float*)d_in[7];
    const float* Wg2    =(const float*)d_in[8];
    const float* bg2    =(const float*)d_in[9];
    const float* log_tau=(const float*)d_in[10];
    const float* omega  =(const float*)d_in[11];
    const float* Wp     =(const float*)d_in[12];
    const float* gamma  =(const float*)d_in[13];
    const float* beta   =(const float*)d_in[14];
    float* out=(float*)d_out;

    qk_gemm     <<<dim3(64,BB),256>>>(x,Wq,Wk);                                      // 0
    v_tf32      <<<dim3(64,2,BB),256>>>(x,Wv);                                       // 1
    feat_kernel <<<dim3(64,BB),128>>>(pos,proj_sm,Wg1,bg1,Wg2,bg2,log_tau,omega);    // 2
    kv_tf32     <<<dim3(16,2,BB),256>>>();                                           // 3 (ncu slot)
    ksum_part   <<<dim3(32,BB),256>>>();                                             // 4
    ksum_reduce <<<dim3(8,BB),256>>>();                                              // 5
    denom_kernel<<<dim3(32,BB),256>>>();                                             // 6
    fsa_tf32    <<<dim3(64,2,BB),256>>>();                                           // 7
    h_tf32      <<<dim3(2,64,BB),256>>>(x,Wp);                                       // 8
    stats_kernel<<<1,256>>>(gamma,beta);                                             // 9
    final_kernel<<<8192,256>>>(x,out);                                               // 10
}

// round 5
// speedup vs baseline: 2.4066x; 1.0956x over previous
#include <cuda_runtime.h>
#include <math.h>
#include <stdint.h>

#define BB 4
#define CC 256
#define NN 8192
#define RSM 128
#define RG 16
#define RR 2048       // RSM*RG
#define NTILES 64     // NN/128

// ---------------- scratch (static device globals; no allocation) ----------------
__device__ float g_qk [(size_t)BB*NN*128];     // [b][n][0:64 q,64:128 k]
__device__ float g_v  [(size_t)BB*NN*256];     // [b][n][c]
__device__ float g_qp [(size_t)BB*NN*RSM];
__device__ float g_kp [(size_t)BB*NN*RSM];
__device__ float g_phi[(size_t)BB*NN*RG];
__device__ float g_kv [(size_t)BB*RR*CC];
__device__ float g_kvpart[(size_t)BB*2*RR*CC]; // split-K partials
__device__ float g_ksum[(size_t)BB*RR];
__device__ float g_kspart[(size_t)BB*32*RR];
__device__ float g_denom[(size_t)BB*NN];
__device__ float g_fsa[(size_t)BB*NN*CC];
__device__ float g_h  [(size_t)BB*CC*NN];
__device__ float g_psum  [(size_t)BB*NTILES*CC];
__device__ float g_psumsq[(size_t)BB*NTILES*CC];
__device__ float g_scale[CC];
__device__ float g_bias [CC];

#define ROWQ(g,m) (((m)<4) ? ((g)*4+(m)) : (64+(g)*4+((m)-4)))

// ================= tf32 warp-MMA helpers =========================================
__device__ __forceinline__ uint32_t f2tf32(float f){
    uint32_t r; asm("cvt.rna.tf32.f32 %0, %1;" : "=r"(r) : "f"(f)); return r;
}
__device__ __forceinline__ void mma_tf32(float* c,
    uint32_t a0, uint32_t a1, uint32_t a2, uint32_t a3, uint32_t b0, uint32_t b1){
    asm volatile(
      "mma.sync.aligned.m16n8k8.row.col.f32.tf32.tf32.f32 "
      "{%0,%1,%2,%3},{%4,%5,%6,%7},{%8,%9},{%0,%1,%2,%3};"
      : "+f"(c[0]),"+f"(c[1]),"+f"(c[2]),"+f"(c[3])
      : "r"(a0),"r"(a1),"r"(a2),"r"(a3),"r"(b0),"r"(b1));
}

// MMA inner phase over a 32-deep K chunk (warp tile 64x64): As[k][m], Bs[k][c]
__device__ __forceinline__ void mma_chunk64(const uint32_t (*As)[136], const uint32_t (*Bs)[264],
                                            float acc[4][8][4], int m_base, int c_base, int lane){
    #pragma unroll
    for(int ks=0;ks<32;ks+=8){
        const int kk=ks+(lane&3);
        uint32_t af[4][4], bf[8][2];
        #pragma unroll
        for(int mf=0;mf<4;mf++){
            int m0=m_base+mf*16+(lane>>2);
            af[mf][0]=As[kk][m0];
            af[mf][1]=As[kk][m0+8];
            af[mf][2]=As[kk+4][m0];
            af[mf][3]=As[kk+4][m0+8];
        }
        #pragma unroll
        for(int nf=0;nf<8;nf++){
            int c0=c_base+nf*8+(lane>>2);
            bf[nf][0]=Bs[kk][c0];
            bf[nf][1]=Bs[kk+4][c0];
        }
        #pragma unroll
        for(int mf=0;mf<4;mf++)
            #pragma unroll
            for(int nf=0;nf<8;nf++)
                mma_tf32(acc[mf][nf],af[mf][0],af[mf][1],af[mf][2],af[mf][3],bf[nf][0],bf[nf][1]);
    }
}

// MMA inner phase, warp tile 64x32 (for v_tf32 / h_tf32)
__device__ __forceinline__ void mma_chunk(const uint32_t (*As)[136], const uint32_t (*Bs)[136],
                                          float acc[4][4][4], int m_base, int c_base, int lane){
    #pragma unroll
    for(int ks=0;ks<32;ks+=8){
        uint32_t af[4][4], bf[4][2];
        const int kk=ks+(lane&3);
        #pragma unroll
        for(int mf=0;mf<4;mf++){
            int m0=m_base+mf*16+(lane>>2);
            af[mf][0]=As[kk][m0];
            af[mf][1]=As[kk][m0+8];
            af[mf][2]=As[kk+4][m0];
            af[mf][3]=As[kk+4][m0+8];
        }
        #pragma unroll
        for(int nf=0;nf<4;nf++){
            int c0=c_base+nf*8+(lane>>2);
            bf[nf][0]=Bs[kk][c0];
            bf[nf][1]=Bs[kk+4][c0];
        }
        #pragma unroll
        for(int mf=0;mf<4;mf++)
            #pragma unroll
            for(int nf=0;nf<4;nf++)
                mma_tf32(acc[mf][nf],af[mf][0],af[mf][1],af[mf][2],af[mf][3],bf[nf][0],bf[nf][1]);
    }
}

// =========================== FFMA helper =========================================
__device__ __forceinline__ void mma16(const float (*As)[132], const float (*Bs)[132],
                                      float acc[8][8], int ty, int tx){
    #pragma unroll
    for(int kk=0;kk<16;kk++){
        float a[8], bv[8];
        *(float4*)(a)    = *(const float4*)&As[kk][ty*4];
        *(float4*)(a+4)  = *(const float4*)&As[kk][64+ty*4];
        *(float4*)(bv)   = *(const float4*)&Bs[kk][tx*4];
        *(float4*)(bv+4) = *(const float4*)&Bs[kk][64+tx*4];
        #pragma unroll
        for(int m=0;m<8;m++)
            #pragma unroll
            for(int n=0;n<8;n++)
                acc[m][n]=fmaf(a[m],bv[n],acc[m][n]);
    }
}

// ---------------- kernel: QK = X^T @ [Wq;Wk]^T (scaled), fp32 --------------------
__global__ __launch_bounds__(256) void qk_gemm(const float* __restrict__ x,
    const float* __restrict__ Wq, const float* __restrict__ Wk)
{
    __shared__ float As[16][132];
    __shared__ float Bs[16][132];
    int nt=blockIdx.x, b=blockIdx.y;
    int n0=nt*128;
    int tid=threadIdx.x, ty=tid>>4, tx=tid&15;
    float acc[8][8]={};
    for(int c0=0;c0<256;c0+=16){
        #pragma unroll
        for(int l=0;l<2;l++){
            int f4=tid+l*256;
            int kk=f4>>5, n4=(f4&31)<<2;
            *(float4*)&As[kk][n4] = *(const float4*)(x + ((size_t)b*CC + c0+kk)*NN + n0+n4);
            int oo=f4>>2, kc=(f4&3)<<2;
            const float* wr = (oo<64)? (Wq+(size_t)oo*CC) : (Wk+(size_t)(oo-64)*CC);
            float4 w=*(const float4*)(wr + c0+kc);
            Bs[kc+0][oo]=w.x; Bs[kc+1][oo]=w.y; Bs[kc+2][oo]=w.z; Bs[kc+3][oo]=w.w;
        }
        __syncthreads();
        mma16(As,Bs,acc,ty,tx);
        __syncthreads();
    }
    const float s = 0.3535533905932738f;   // 64^-0.25
    #pragma unroll
    for(int m=0;m<8;m++){
        int n=n0+ROWQ(ty,m);
        size_t base=((size_t)b*NN+n)*128;
        float4 v0={acc[m][0]*s,acc[m][1]*s,acc[m][2]*s,acc[m][3]*s};
        float4 v1={acc[m][4]*s,acc[m][5]*s,acc[m][6]*s,acc[m][7]*s};
        *(float4*)&g_qk[base+tx*4]=v0;
        *(float4*)&g_qk[base+64+tx*4]=v1;
    }
}

// ---------------- kernel: V = X^T @ Wv^T (tf32 mma) ------------------------------
__global__ __launch_bounds__(256) void v_tf32(const float* __restrict__ x, const float* __restrict__ Wv)
{
    __shared__ uint32_t As[32][136];   // [k=c][n]
    __shared__ uint32_t Bs[32][136];   // [k=c][o]
    const int nt=blockIdx.x, ct=blockIdx.y, b=blockIdx.z;
    const int tid=threadIdx.x, lane=tid&31, wid=tid>>5;
    const int m_base=(wid>>2)*64, c_base=(wid&3)*32;
    const int n0=nt*128;

    float4 rA[4], rW[4];
    #pragma unroll
    for(int l=0;l<4;l++){
        int f4=tid+l*256;
        int kk=f4>>5, n4=(f4&31)<<2;
        rA[l]=*(const float4*)(x + ((size_t)b*CC + kk)*NN + n0+n4);
        int oo=f4>>3, kc4=(f4&7)<<2;
        rW[l]=*(const float4*)(Wv + (size_t)(ct*128+oo)*CC + kc4);
    }
    float acc[4][4][4];
    #pragma unroll
    for(int a=0;a<4;a++)
        #pragma unroll
        for(int bq=0;bq<4;bq++)
            #pragma unroll
            for(int cq=0;cq<4;cq++) acc[a][bq][cq]=0.0f;

    for(int it=0; it<8; ++it){
        __syncthreads();
        #pragma unroll
        for(int l=0;l<4;l++){
            int f4=tid+l*256;
            int kk=f4>>5, n4=(f4&31)<<2;
            uint4 u={f2tf32(rA[l].x),f2tf32(rA[l].y),f2tf32(rA[l].z),f2tf32(rA[l].w)};
            *(uint4*)&As[kk][n4]=u;
            int oo=f4>>3, kc=(f4&7)<<2;
            Bs[kc+0][oo]=f2tf32(rW[l].x); Bs[kc+1][oo]=f2tf32(rW[l].y);
            Bs[kc+2][oo]=f2tf32(rW[l].z); Bs[kc+3][oo]=f2tf32(rW[l].w);
        }
        __syncthreads();
        if(it+1<8){
            int c0=(it+1)*32;
            #pragma unroll
            for(int l=0;l<4;l++){
                int f4=tid+l*256;
                int kk=f4>>5, n4=(f4&31)<<2;
                rA[l]=*(const float4*)(x + ((size_t)b*CC + c0+kk)*NN + n0+n4);
                int oo=f4>>3, kc4=(f4&7)<<2;
                rW[l]=*(const float4*)(Wv + (size_t)(ct*128+oo)*CC + c0+kc4);
            }
        }
        mma_chunk(As,Bs,acc,m_base,c_base,lane);
    }
    #pragma unroll
    for(int mf=0;mf<4;mf++){
        int m = m_base + mf*16 + (lane>>2);
        #pragma unroll
        for(int nf=0;nf<4;nf++){
            int c = ct*128 + c_base + nf*8 + 2*(lane&3);
            float2 v0={acc[mf][nf][0],acc[mf][nf][1]};
            float2 v1={acc[mf][nf][2],acc[mf][nf][3]};
            *(float2*)&g_v[((size_t)b*NN + n0+m)*256 + c]   = v0;
            *(float2*)&g_v[((size_t)b*NN + n0+m+8)*256 + c] = v1;
        }
    }
}

// ---------------- feature maps (q_p, k_p) and geo RFF (phi) ----------------------
__global__ __launch_bounds__(128) void feat_kernel(const float* __restrict__ pos,
    const float* __restrict__ P,  const float* __restrict__ Wg1, const float* __restrict__ bg1,
    const float* __restrict__ Wg2,const float* __restrict__ bg2, const float* __restrict__ logtau,
    const float* __restrict__ omega)
{
    __shared__ float Ps[4096];
    __shared__ float Om[256];
    __shared__ float sWg1[48], sbg1[16], sWg2[256], sbg2[16];
    int tid=threadIdx.x;
    for(int i=tid;i<4096;i+=128) Ps[i]=P[i];
    for(int i=tid;i<256;i+=128){ Om[i]=omega[i]; sWg2[i]=Wg2[i]; }
    if(tid<48) sWg1[tid]=Wg1[tid];
    if(tid<16){ sbg1[tid]=bg1[tid]; sbg2[tid]=bg2[tid]; }
    __syncthreads();

    int b=blockIdx.y;
    int n=blockIdx.x*128 + tid;
    size_t bn=(size_t)b*NN + n;

    float lt=logtau[0];
    float tau=log1pf(expf(lt)) + 1e-6f;
    float s2t=sqrtf(2.0f*tau);
    float p0=pos[bn*3+0], p1=pos[bn*3+1], p2=pos[bn*3+2];
    float g1[16], z[16];
    #pragma unroll
    for(int d=0;d<16;d++){
        float t=fmaf(sWg1[d*3],p0,fmaf(sWg1[d*3+1],p1,fmaf(sWg1[d*3+2],p2,sbg1[d])));
        g1[d]=fmaxf(t,0.0f);
    }
    float zn=0.0f;
    #pragma unroll
    for(int d=0;d<16;d++){
        float t=sbg2[d];
        #pragma unroll
        for(int e=0;e<16;e++) t=fmaf(sWg2[d*16+e],g1[e],t);
        z[d]=t*s2t;
        zn=fmaf(z[d],z[d],zn);
    }
    zn*=0.5f;
    #pragma unroll
    for(int r=0;r<16;r++){
        float t=0.0f;
        #pragma unroll
        for(int d=0;d<16;d++) t=fmaf(z[d],Om[d*16+r],t);
        g_phi[bn*16+r]=expf(t-zn)*0.25f;
    }

    const float* row = g_qk + bn*128;
    const float fs = 0.08838834764831845f;
    for(int which=0;which<2;which++){
        const float* qr = row + which*64;
        float proj[64];
        #pragma unroll
        for(int m=0;m<64;m++) proj[m]=0.0f;
        for(int o=0;o<64;o++){
            float qo=qr[o];
            #pragma unroll
            for(int m=0;m<64;m++) proj[m]=fmaf(qo,Ps[o*64+m],proj[m]);
        }
        float M=0.0f;
        #pragma unroll
        for(int m=0;m<64;m++) M=fmaxf(M,fabsf(proj[m]));
        float* dst=(which==0? g_qp : g_kp) + bn*128;
        #pragma unroll
        for(int m=0;m<64;m++){
            dst[m]    = expf(proj[m]-M)*fs + 1e-6f;
            dst[64+m] = expf(-proj[m]-M)*fs + 1e-6f;
        }
    }
}

// ---------------- ksum: partial + reduce -----------------------------------------
__global__ __launch_bounds__(256) void ksum_part()
{
    __shared__ float skp[64][128];
    __shared__ float sph[64][16];
    int t=threadIdx.x;
    int ch=blockIdx.x, b=blockIdx.y;
    int nbase=ch*256;
    float acc[8]={};
    int iidx[8], jidx[8];
    #pragma unroll
    for(int k=0;k<8;k++){ int r=t+k*256; iidx[k]=r>>4; jidx[k]=r&15; }
    for(int sub=0;sub<4;sub++){
        int ns=nbase+sub*64;
        __syncthreads();
        #pragma unroll
        for(int l=0;l<8;l++){
            int f4=t+l*256; int row=f4>>5, c4=f4&31;
            *(float4*)&skp[row][c4*4]=*(const float4*)(g_kp+((size_t)b*NN+ns+row)*128+c4*4);
        }
        { int row=t>>2, c4=t&3;
          *(float4*)&sph[row][c4*4]=*(const float4*)(g_phi+((size_t)b*NN+ns+row)*16+c4*4); }
        __syncthreads();
        for(int n=0;n<64;n++){
            #pragma unroll
            for(int k=0;k<8;k++) acc[k]=fmaf(skp[n][iidx[k]],sph[n][jidx[k]],acc[k]);
        }
    }
    #pragma unroll
    for(int k=0;k<8;k++) g_kspart[((size_t)b*32+ch)*RR + t + k*256]=acc[k];
}

__global__ void ksum_reduce()
{
    int r=blockIdx.x*256+threadIdx.x; int b=blockIdx.y;
    float s=0.0f;
    #pragma unroll 8
    for(int c=0;c<32;c++) s+=g_kspart[((size_t)b*32+c)*RR + r];
    g_ksum[(size_t)b*RR + r]=s;
}

// ---------------- denom[b][n] = Phi_q[n]·k_sum + eps ------------------------------
__global__ __launch_bounds__(256) void denom_kernel()
{
    __shared__ float ks[2048];
    int b=blockIdx.y;
    for(int i=threadIdx.x;i<2048;i+=256) ks[i]=g_ksum[(size_t)b*RR+i];
    __syncthreads();
    int n=blockIdx.x*256 + threadIdx.x;
    size_t bn=(size_t)b*NN+n;
    float ph[16];
    #pragma unroll
    for(int r=0;r<16;r++) ph[r]=g_phi[bn*16+r];
    float d=0.0f;
    for(int i=0;i<128;i++){
        float t=0.0f;
        #pragma unroll
        for(int jj=0;jj<16;jj++) t=fmaf(ks[i*16+jj],ph[jj],t);
        d=fmaf(g_qp[bn*128+i],t,d);
    }
    g_denom[bn]=d+1e-6f;
}

// ================= tf32 mma GEMM 1: kv (split-K=2, CTA 128x256, dbuf) ============
// kvpart[b][sk][r][c] = sum_{n in half sk} (kp[n,i(r)]*phi[n,j(r)]) * v[n,c]
#define KVFSA_SMEM (2*32*136*4 + 2*32*264*4)   // 102400 bytes
__global__ void __launch_bounds__(256,1) kv_tf32()
{
    extern __shared__ uint32_t smu[];
    uint32_t (*As)[136] = (uint32_t(*)[136])smu;               // [2*32][136]
    uint32_t (*Bs)[264] = (uint32_t(*)[264])(smu + 2*32*136);  // [2*32][264]
    const int mt=blockIdx.x, sk=blockIdx.y, b=blockIdx.z;
    const int tid=threadIdx.x, lane=tid&31, wid=tid>>5;
    const int m_base=(wid>>2)*64, c_base=(wid&3)*64;
    const size_t bn=(size_t)b*NN;
    const int i0=mt*8;
    const int nstart = sk*4096;
    const float* vbase = g_v + (bn+nstart)*256;
    const int skk=tid>>3, si=tid&7;

    float4 rB[8]; float rphi[16]; float rkp;
    #pragma unroll
    for(int l=0;l<8;l++){ int f4=tid+l*256; int row=f4>>6, c4=(f4&63)<<2;
        rB[l]=*(const float4*)(vbase + (size_t)row*256 + c4); }
    {
        const float* ph=g_phi + (bn+nstart+skk)*16;
        #pragma unroll
        for(int q=0;q<4;q++) *(float4*)(rphi+q*4)=*(const float4*)(ph+q*4);
        rkp = g_kp[(bn+nstart+skk)*128 + i0+si];
    }
    float acc[4][8][4];
    #pragma unroll
    for(int a=0;a<4;a++)
        #pragma unroll
        for(int bq=0;bq<8;bq++)
            #pragma unroll
            for(int cq=0;cq<4;cq++) acc[a][bq][cq]=0.0f;

    for(int it=0; it<128; ++it){
        const int buf=(it&1)*32;
        #pragma unroll
        for(int l=0;l<8;l++){ int f4=tid+l*256; int row=f4>>6, c4=(f4&63)<<2;
            uint4 u={f2tf32(rB[l].x),f2tf32(rB[l].y),f2tf32(rB[l].z),f2tf32(rB[l].w)};
            *(uint4*)&Bs[buf+row][c4]=u; }
        {
            uint32_t av[16];
            #pragma unroll
            for(int j=0;j<16;j++) av[j]=f2tf32(rkp*rphi[j]);
            #pragma unroll
            for(int q=0;q<4;q++) *(uint4*)&As[buf+skk][si*16+q*4]=*(uint4*)(av+q*4);
        }
        __syncthreads();
        if(it+1<128){
            int n0=nstart+(it+1)*32;
            #pragma unroll
            for(int l=0;l<8;l++){ int f4=tid+l*256; int row=f4>>6, c4=(f4&63)<<2;
                rB[l]=*(const float4*)(g_v + (bn+n0+row)*256 + c4); }
            const float* ph=g_phi + (bn+n0+skk)*16;
            #pragma unroll
            for(int q=0;q<4;q++) *(float4*)(rphi+q*4)=*(const float4*)(ph+q*4);
            rkp = g_kp[(bn+n0+skk)*128 + i0+si];
        }
        mma_chunk64(As+buf,Bs+buf,acc,m_base,c_base,lane);
    }
    float* dst = g_kvpart + ((size_t)b*2+sk)*RR*CC;
    #pragma unroll
    for(int mf=0;mf<4;mf++){
        int m = mt*128 + m_base + mf*16 + (lane>>2);
        #pragma unroll
        for(int nf=0;nf<8;nf++){
            int c = c_base + nf*8 + 2*(lane&3);
            float2 v0={acc[mf][nf][0],acc[mf][nf][1]};
            float2 v1={acc[mf][nf][2],acc[mf][nf][3]};
            *(float2*)&dst[(size_t)m*CC + c]     = v0;
            *(float2*)&dst[(size_t)(m+8)*CC + c] = v1;
        }
    }
}

// kv = part0 + part1
__global__ __launch_bounds__(256) void kv_reduce()
{
    size_t i4=(size_t)blockIdx.x*256 + threadIdx.x;
    size_t f=i4*4;
    size_t b=f/((size_t)RR*CC), off=f%((size_t)RR*CC);
    float4 a=*(const float4*)(g_kvpart + (b*2+0)*(size_t)RR*CC + off);
    float4 c=*(const float4*)(g_kvpart + (b*2+1)*(size_t)RR*CC + off);
    float4 o={a.x+c.x,a.y+c.y,a.z+c.z,a.w+c.w};
    *(float4*)(g_kv + b*(size_t)RR*CC + off)=o;
}

// ================= tf32 mma GEMM 2: fsa (CTA 128x256, dbuf) ======================
// fsa[b][n][c] = (sum_r (qp[n,i(r)]*phi[n,j(r)]) * kv[r,c]) / denom[n]
__global__ void __launch_bounds__(256,1) fsa_tf32()
{
    extern __shared__ uint32_t smu[];
    uint32_t (*As)[136] = (uint32_t(*)[136])smu;
    uint32_t (*Bs)[264] = (uint32_t(*)[264])(smu + 2*32*136);
    const int mt=blockIdx.x, b=blockIdx.z;
    const int tid=threadIdx.x, lane=tid&31, wid=tid>>5;
    const int m_base=(wid>>2)*64, c_base=(wid&3)*64;
    const size_t bn0=(size_t)b*NN + (size_t)mt*128;
    const float* kvbase = g_kv + (size_t)b*RR*CC;
    const int sm=tid>>1, sip=tid&1;

    float rphi[16];
    {
        const float* ph=g_phi + (bn0+sm)*16;
        #pragma unroll
        for(int q=0;q<4;q++) *(float4*)(rphi+q*4)=*(const float4*)(ph+q*4);
    }
    float4 rB[8]; float rqp;
    #pragma unroll
    for(int l=0;l<8;l++){ int f4=tid+l*256; int row=f4>>6, c4=(f4&63)<<2;
        rB[l]=*(const float4*)(kvbase + (size_t)row*CC + c4); }
    rqp = g_qp[(bn0+sm)*128 + sip];

    float acc[4][8][4];
    #pragma unroll
    for(int a=0;a<4;a++)
        #pragma unroll
        for(int bq=0;bq<8;bq++)
            #pragma unroll
            for(int cq=0;cq<4;cq++) acc[a][bq][cq]=0.0f;

    for(int it=0; it<64; ++it){
        const int buf=(it&1)*32;
        #pragma unroll
        for(int l=0;l<8;l++){ int f4=tid+l*256; int row=f4>>6, c4=(f4&63)<<2;
            uint4 u={f2tf32(rB[l].x),f2tf32(rB[l].y),f2tf32(rB[l].z),f2tf32(rB[l].w)};
            *(uint4*)&Bs[buf+row][c4]=u; }
        {
            #pragma unroll
            for(int j=0;j<16;j++) As[buf+sip*16+j][sm]=f2tf32(rqp*rphi[j]);
        }
        __syncthreads();
        if(it+1<64){
            int k0=(it+1)*32;
            #pragma unroll
            for(int l=0;l<8;l++){ int f4=tid+l*256; int row=f4>>6, c4=(f4&63)<<2;
                rB[l]=*(const float4*)(kvbase + (size_t)(k0+row)*CC + c4); }
            rqp = g_qp[(bn0+sm)*128 + (it+1)*2 + sip];
        }
        mma_chunk64(As+buf,Bs+buf,acc,m_base,c_base,lane);
    }
    #pragma unroll
    for(int mf=0;mf<4;mf++){
        int ml = m_base + mf*16 + (lane>>2);
        float inv0 = 1.0f/g_denom[bn0+ml];
        float inv1 = 1.0f/g_denom[bn0+ml+8];
        #pragma unroll
        for(int nf=0;nf<8;nf++){
            int c = c_base + nf*8 + 2*(lane&3);
            float2 v0={acc[mf][nf][0]*inv0,acc[mf][nf][1]*inv0};
            float2 v1={acc[mf][nf][2]*inv1,acc[mf][nf][3]*inv1};
            *(float2*)&g_fsa[(bn0+ml)*CC + c]   = v0;
            *(float2*)&g_fsa[(bn0+ml+8)*CC + c] = v1;
        }
    }
}

// ---------------- h = Wp @ (x - fsa^T) (tf32 mma) + BN partials -------------------
__global__ __launch_bounds__(256) void h_tf32(const float* __restrict__ x, const float* __restrict__ Wp)
{
    __shared__ uint32_t As[32][136];   // [k=c][o] tf32 Wp
    __shared__ uint32_t Bs[32][136];   // [k=c][n] tf32 (x - fsa)
    __shared__ float red[128][5];
    const int mt=blockIdx.x, nt=blockIdx.y, b=blockIdx.z;
    const int o0=mt*128, n0=nt*128;
    const int tid=threadIdx.x, lane=tid&31, wid=tid>>5;
    const int m_base=(wid>>2)*64, c_base=(wid&3)*32;

    float4 rW[4], rF[4], rX[4];
    #pragma unroll
    for(int l=0;l<4;l++){
        int f4=tid+l*256;
        int oo=f4>>3, kc4=(f4&7)<<2;
        rW[l]=*(const float4*)(Wp + (size_t)(o0+oo)*CC + kc4);
        rF[l]=*(const float4*)(g_fsa + ((size_t)b*NN+n0+oo)*CC + kc4);
        int kk=f4>>5, n4=(f4&31)<<2;
        rX[l]=*(const float4*)(x + ((size_t)b*CC+kk)*NN + n0+n4);
    }
    float acc[4][4][4];
    #pragma unroll
    for(int a=0;a<4;a++)
        #pragma unroll
        for(int bq=0;bq<4;bq++)
            #pragma unroll
            for(int cq=0;cq<4;cq++) acc[a][bq][cq]=0.0f;

    for(int it=0; it<8; ++it){
        __syncthreads();
        #pragma unroll
        for(int l=0;l<4;l++){
            int f4=tid+l*256;
            int oo=f4>>3, kc=(f4&7)<<2;
            As[kc+0][oo]=f2tf32(rW[l].x); As[kc+1][oo]=f2tf32(rW[l].y);
            As[kc+2][oo]=f2tf32(rW[l].z); As[kc+3][oo]=f2tf32(rW[l].w);
            Bs[kc+0][oo]=__float_as_uint(-rF[l].x); Bs[kc+1][oo]=__float_as_uint(-rF[l].y);
            Bs[kc+2][oo]=__float_as_uint(-rF[l].z); Bs[kc+3][oo]=__float_as_uint(-rF[l].w);
        }
        __syncthreads();
        #pragma unroll
        for(int l=0;l<4;l++){
            int f4=tid+l*256;
            int kk=f4>>5, n4=(f4&31)<<2;
            uint4 cur=*(uint4*)&Bs[kk][n4];
            cur.x=f2tf32(__uint_as_float(cur.x)+rX[l].x);
            cur.y=f2tf32(__uint_as_float(cur.y)+rX[l].y);
            cur.z=f2tf32(__uint_as_float(cur.z)+rX[l].z);
            cur.w=f2tf32(__uint_as_float(cur.w)+rX[l].w);
            *(uint4*)&Bs[kk][n4]=cur;
        }
        __syncthreads();
        if(it+1<8){
            int c0=(it+1)*32;
            #pragma unroll
            for(int l=0;l<4;l++){
                int f4=tid+l*256;
                int oo=f4>>3, kc4=(f4&7)<<2;
                rW[l]=*(const float4*)(Wp + (size_t)(o0+oo)*CC + c0+kc4);
                rF[l]=*(const float4*)(g_fsa + ((size_t)b*NN+n0+oo)*CC + c0+kc4);
                int kk=f4>>5, n4=(f4&31)<<2;
                rX[l]=*(const float4*)(x + ((size_t)b*CC+c0+kk)*NN + n0+n4);
            }
        }
        mma_chunk(As,Bs,acc,m_base,c_base,lane);
    }
    #pragma unroll
    for(int mf=0;mf<4;mf++){
        int r0 = m_base + mf*16 + (lane>>2);
        #pragma unroll
        for(int nf=0;nf<4;nf++){
            int nl = c_base + nf*8 + 2*(lane&3);
            float2 v0={acc[mf][nf][0],acc[mf][nf][1]};
            float2 v1={acc[mf][nf][2],acc[mf][nf][3]};
            *(float2*)&g_h[((size_t)b*CC + o0+r0)*NN + n0+nl]   = v0;
            *(float2*)&g_h[((size_t)b*CC + o0+r0+8)*NN + n0+nl] = v1;
        }
    }
    float s[4][2], q2[4][2];
    #pragma unroll
    for(int mf=0;mf<4;mf++){
        float a0=0.f,a1=0.f,b0=0.f,b1=0.f;
        #pragma unroll
        for(int nf=0;nf<4;nf++){
            a0+=acc[mf][nf][0]+acc[mf][nf][1];
            b0+=acc[mf][nf][0]*acc[mf][nf][0]+acc[mf][nf][1]*acc[mf][nf][1];
            a1+=acc[mf][nf][2]+acc[mf][nf][3];
            b1+=acc[mf][nf][2]*acc[mf][nf][2]+acc[mf][nf][3]*acc[mf][nf][3];
        }
        s[mf][0]=a0; s[mf][1]=a1; q2[mf][0]=b0; q2[mf][1]=b1;
    }
    #pragma unroll
    for(int mf=0;mf<4;mf++)
        #pragma unroll
        for(int hh=0;hh<2;hh++){
            s[mf][hh]  += __shfl_xor_sync(0xffffffff, s[mf][hh], 1);
            s[mf][hh]  += __shfl_xor_sync(0xffffffff, s[mf][hh], 2);
            q2[mf][hh] += __shfl_xor_sync(0xffffffff, q2[mf][hh], 1);
            q2[mf][hh] += __shfl_xor_sync(0xffffffff, q2[mf][hh], 2);
        }
    __syncthreads();
    if((lane&3)==0){
        #pragma unroll
        for(int mf=0;mf<4;mf++)
            #pragma unroll
            for(int hh=0;hh<2;hh++)
                red[m_base+mf*16+(lane>>2)+hh*8][wid&3]=s[mf][hh];
    }
    __syncthreads();
    if(tid<128){
        float t=red[tid][0]+red[tid][1]+red[tid][2]+red[tid][3];
        g_psum[((size_t)b*NTILES+nt)*CC + o0 + tid]=t;
    }
    __syncthreads();
    if((lane&3)==0){
        #pragma unroll
        for(int mf=0;mf<4;mf++)
            #pragma unroll
            for(int hh=0;hh<2;hh++)
                red[m_base+mf*16+(lane>>2)+hh*8][wid&3]=q2[mf][hh];
    }
    __syncthreads();
    if(tid<128){
        float t=red[tid][0]+red[tid][1]+red[tid][2]+red[tid][3];
        g_psumsq[((size_t)b*NTILES+nt)*CC + o0 + tid]=t;
    }
}

// ---------------- BN stats -> scale/bias ------------------------------------------
__global__ void stats_kernel(const float* __restrict__ gamma, const float* __restrict__ beta)
{
    int o=threadIdx.x;
    float s=0.f,s2=0.f;
    for(int t=0;t<BB*NTILES;t++){
        s +=g_psum  [(size_t)t*CC+o];
        s2+=g_psumsq[(size_t)t*CC+o];
    }
    const float inv=1.0f/(float)((size_t)BB*NN);
    float mean=s*inv;
    float var=s2*inv - mean*mean;
    float sc=gamma[o]*rsqrtf(var+1e-5f);
    g_scale[o]=sc;
    g_bias[o]=beta[o]-mean*sc;
}

// ---------------- out = relu(BN(h)) + x --------------------------------------------
__global__ __launch_bounds__(256) void final_kernel(const float* __restrict__ x, float* __restrict__ out)
{
    size_t i4=(size_t)blockIdx.x*256 + threadIdx.x;
    size_t f=i4*4;
    int c=(int)((f/NN)%CC);
    float sc=g_scale[c], bi=g_bias[c];
    float4 h=*(const float4*)(g_h+f);
    float4 xv=*(const float4*)(x+f);
    float4 o;
    o.x=fmaxf(fmaf(h.x,sc,bi),0.0f)+xv.x;
    o.y=fmaxf(fmaf(h.y,sc,bi),0.0f)+xv.y;
    o.z=fmaxf(fmaf(h.z,sc,bi),0.0f)+xv.z;
    o.w=fmaxf(fmaf(h.w,sc,bi),0.0f)+xv.w;
    *(float4*)(out+f)=o;
}

// ---------------- launch ------------------------------------------------------------
extern "C" void kernel_launch(void* const* d_in, const int* in_sizes, int n_in,
                              void* d_out, int out_size)
{
    const float* x      =(const float*)d_in[0];
    const float* pos    =(const float*)d_in[1];
    const float* Wq     =(const float*)d_in[2];
    const float* Wk     =(const float*)d_in[3];
    const float* Wv     =(const float*)d_in[4];
    const float* proj_sm=(const float*)d_in[5];
    const float* Wg1    =(const float*)d_in[6];
    const float* bg1    =(const float*)d_in[7];
    const float* Wg2    =(const float*)d_in[8];
    const float* bg2    =(const float*)d_in[9];
    const float* log_tau=(const float*)d_in[10];
    const float* omega  =(const float*)d_in[11];
    const float* Wp     =(const float*)d_in[12];
    const float* gamma  =(const float*)d_in[13];
    const float* beta   =(const float*)d_in[14];
    float* out=(float*)d_out;

    static int smem_set = 0;
    if(!smem_set){
        cudaFuncSetAttribute(kv_tf32,  cudaFuncAttributeMaxDynamicSharedMemorySize, KVFSA_SMEM);
        cudaFuncSetAttribute(fsa_tf32, cudaFuncAttributeMaxDynamicSharedMemorySize, KVFSA_SMEM);
        smem_set = 1;
    }

    qk_gemm     <<<dim3(64,BB),256>>>(x,Wq,Wk);                                      // 0
    v_tf32      <<<dim3(64,2,BB),256>>>(x,Wv);                                       // 1
    feat_kernel <<<dim3(64,BB),128>>>(pos,proj_sm,Wg1,bg1,Wg2,bg2,log_tau,omega);    // 2
    kv_tf32     <<<dim3(16,2,BB),256,KVFSA_SMEM>>>();                                // 3 (ncu slot)
    kv_reduce   <<<2048,256>>>();                                                    // 4
    ksum_part   <<<dim3(32,BB),256>>>();                                             // 5
    ksum_reduce <<<dim3(8,BB),256>>>();                                              // 6
    denom_kernel<<<dim3(32,BB),256>>>();                                             // 7
    fsa_tf32    <<<dim3(64,1,BB),256,KVFSA_SMEM>>>();                                // 8
    h_tf32      <<<dim3(2,64,BB),256>>>(x,Wp);                                       // 9
    stats_kernel<<<1,256>>>(gamma,beta);                                             // 10
    final_kernel<<<8192,256>>>(x,out);                                               // 11
}

// round 6
// speedup vs baseline: 2.5407x; 1.0557x over previous
#include <cuda_runtime.h>
#include <math.h>
#include <stdint.h>

#define BB 4
#define CC 256
#define NN 8192
#define RSM 128
#define RG 16
#define RR 2048       // RSM*RG
#define NTILES 64     // NN/128

// ---------------- scratch (static device globals; no allocation) ----------------
__device__ float g_qk [(size_t)BB*NN*128];     // [b][n][0:64 q,64:128 k]
__device__ float g_v  [(size_t)BB*NN*256];     // [b][n][c]
__device__ float g_qp [(size_t)BB*NN*RSM];
__device__ float g_kp [(size_t)BB*NN*RSM];
__device__ float g_phi[(size_t)BB*NN*RG];
__device__ float g_kv [(size_t)BB*RR*CC];
__device__ float g_kvpart[(size_t)BB*2*RR*CC]; // split-K partials
__device__ float g_ksum[(size_t)BB*RR];
__device__ float g_kspart[(size_t)BB*32*RR];
__device__ float g_denom[(size_t)BB*NN];
__device__ float g_fsa[(size_t)BB*NN*CC];
__device__ float g_h  [(size_t)BB*CC*NN];
__device__ float g_psum  [(size_t)BB*NTILES*CC];
__device__ float g_psumsq[(size_t)BB*NTILES*CC];
__device__ float g_scale[CC];
__device__ float g_bias [CC];

#define ROWQ(g,m) (((m)<4) ? ((g)*4+(m)) : (64+(g)*4+((m)-4)))

// ================= tf32 warp-MMA helpers =========================================
// NOTE: operands are stored as RAW fp32 bits; HMMA tf32 truncates low mantissa bits
// (CUTLASS round_toward_zero passthrough). No cvt instructions in hot loops.
__device__ __forceinline__ void mma_tf32(float* c,
    uint32_t a0, uint32_t a1, uint32_t a2, uint32_t a3, uint32_t b0, uint32_t b1){
    asm volatile(
      "mma.sync.aligned.m16n8k8.row.col.f32.tf32.tf32.f32 "
      "{%0,%1,%2,%3},{%4,%5,%6,%7},{%8,%9},{%0,%1,%2,%3};"
      : "+f"(c[0]),"+f"(c[1]),"+f"(c[2]),"+f"(c[3])
      : "r"(a0),"r"(a1),"r"(a2),"r"(a3),"r"(b0),"r"(b1));
}

__device__ __forceinline__ uint32_t smem_u32(const void* p){
    uint32_t a; asm("{ .reg .u64 t; cvta.to.shared.u64 t, %1; cvt.u32.u64 %0, t; }":"=r"(a):"l"(p));
    return a;
}
__device__ __forceinline__ void cp16(uint32_t dst, const void* src){
    asm volatile("cp.async.cg.shared.global [%0], [%1], 16;"::"r"(dst),"l"(src):"memory");
}
#define CP_COMMIT() asm volatile("cp.async.commit_group;":::"memory")
#define CP_WAIT0()  asm volatile("cp.async.wait_group 0;":::"memory")

// MMA inner phase over a 32-deep K chunk (warp tile 64x64): As[k][m], Bs[k][c]
__device__ __forceinline__ void mma_chunk64(const uint32_t (*As)[136], const uint32_t (*Bs)[264],
                                            float acc[4][8][4], int m_base, int c_base, int lane){
    #pragma unroll
    for(int ks=0;ks<32;ks+=8){
        const int kk=ks+(lane&3);
        uint32_t af[4][4], bf[8][2];
        #pragma unroll
        for(int mf=0;mf<4;mf++){
            int m0=m_base+mf*16+(lane>>2);
            af[mf][0]=As[kk][m0];
            af[mf][1]=As[kk][m0+8];
            af[mf][2]=As[kk+4][m0];
            af[mf][3]=As[kk+4][m0+8];
        }
        #pragma unroll
        for(int nf=0;nf<8;nf++){
            int c0=c_base+nf*8+(lane>>2);
            bf[nf][0]=Bs[kk][c0];
            bf[nf][1]=Bs[kk+4][c0];
        }
        #pragma unroll
        for(int mf=0;mf<4;mf++)
            #pragma unroll
            for(int nf=0;nf<8;nf++)
                mma_tf32(acc[mf][nf],af[mf][0],af[mf][1],af[mf][2],af[mf][3],bf[nf][0],bf[nf][1]);
    }
}

// MMA inner phase, warp tile 64x32 (for v_tf32 / h_tf32)
__device__ __forceinline__ void mma_chunk(const uint32_t (*As)[136], const uint32_t (*Bs)[136],
                                          float acc[4][4][4], int m_base, int c_base, int lane){
    #pragma unroll
    for(int ks=0;ks<32;ks+=8){
        uint32_t af[4][4], bf[4][2];
        const int kk=ks+(lane&3);
        #pragma unroll
        for(int mf=0;mf<4;mf++){
            int m0=m_base+mf*16+(lane>>2);
            af[mf][0]=As[kk][m0];
            af[mf][1]=As[kk][m0+8];
            af[mf][2]=As[kk+4][m0];
            af[mf][3]=As[kk+4][m0+8];
        }
        #pragma unroll
        for(int nf=0;nf<4;nf++){
            int c0=c_base+nf*8+(lane>>2);
            bf[nf][0]=Bs[kk][c0];
            bf[nf][1]=Bs[kk+4][c0];
        }
        #pragma unroll
        for(int mf=0;mf<4;mf++)
            #pragma unroll
            for(int nf=0;nf<4;nf++)
                mma_tf32(acc[mf][nf],af[mf][0],af[mf][1],af[mf][2],af[mf][3],bf[nf][0],bf[nf][1]);
    }
}

// =========================== FFMA helper =========================================
__device__ __forceinline__ void mma16(const float (*As)[132], const float (*Bs)[132],
                                      float acc[8][8], int ty, int tx){
    #pragma unroll
    for(int kk=0;kk<16;kk++){
        float a[8], bv[8];
        *(float4*)(a)    = *(const float4*)&As[kk][ty*4];
        *(float4*)(a+4)  = *(const float4*)&As[kk][64+ty*4];
        *(float4*)(bv)   = *(const float4*)&Bs[kk][tx*4];
        *(float4*)(bv+4) = *(const float4*)&Bs[kk][64+tx*4];
        #pragma unroll
        for(int m=0;m<8;m++)
            #pragma unroll
            for(int n=0;n<8;n++)
                acc[m][n]=fmaf(a[m],bv[n],acc[m][n]);
    }
}

// ---------------- kernel: QK = X^T @ [Wq;Wk]^T (scaled), fp32 --------------------
__global__ __launch_bounds__(256) void qk_gemm(const float* __restrict__ x,
    const float* __restrict__ Wq, const float* __restrict__ Wk)
{
    __shared__ float As[16][132];
    __shared__ float Bs[16][132];
    int nt=blockIdx.x, b=blockIdx.y;
    int n0=nt*128;
    int tid=threadIdx.x, ty=tid>>4, tx=tid&15;
    float acc[8][8]={};
    for(int c0=0;c0<256;c0+=16){
        #pragma unroll
        for(int l=0;l<2;l++){
            int f4=tid+l*256;
            int kk=f4>>5, n4=(f4&31)<<2;
            *(float4*)&As[kk][n4] = *(const float4*)(x + ((size_t)b*CC + c0+kk)*NN + n0+n4);
            int oo=f4>>2, kc=(f4&3)<<2;
            const float* wr = (oo<64)? (Wq+(size_t)oo*CC) : (Wk+(size_t)(oo-64)*CC);
            float4 w=*(const float4*)(wr + c0+kc);
            Bs[kc+0][oo]=w.x; Bs[kc+1][oo]=w.y; Bs[kc+2][oo]=w.z; Bs[kc+3][oo]=w.w;
        }
        __syncthreads();
        mma16(As,Bs,acc,ty,tx);
        __syncthreads();
    }
    const float s = 0.3535533905932738f;   // 64^-0.25
    #pragma unroll
    for(int m=0;m<8;m++){
        int n=n0+ROWQ(ty,m);
        size_t base=((size_t)b*NN+n)*128;
        float4 v0={acc[m][0]*s,acc[m][1]*s,acc[m][2]*s,acc[m][3]*s};
        float4 v1={acc[m][4]*s,acc[m][5]*s,acc[m][6]*s,acc[m][7]*s};
        *(float4*)&g_qk[base+tx*4]=v0;
        *(float4*)&g_qk[base+64+tx*4]=v1;
    }
}

// ---------------- kernel: V = X^T @ Wv^T (tf32 mma, raw bits) --------------------
__global__ __launch_bounds__(256) void v_tf32(const float* __restrict__ x, const float* __restrict__ Wv)
{
    __shared__ uint32_t As[32][136];   // [k=c][n]
    __shared__ uint32_t Bs[32][136];   // [k=c][o]
    const int nt=blockIdx.x, ct=blockIdx.y, b=blockIdx.z;
    const int tid=threadIdx.x, lane=tid&31, wid=tid>>5;
    const int m_base=(wid>>2)*64, c_base=(wid&3)*32;
    const int n0=nt*128;

    float4 rA[4], rW[4];
    #pragma unroll
    for(int l=0;l<4;l++){
        int f4=tid+l*256;
        int kk=f4>>5, n4=(f4&31)<<2;
        rA[l]=*(const float4*)(x + ((size_t)b*CC + kk)*NN + n0+n4);
        int oo=f4>>3, kc4=(f4&7)<<2;
        rW[l]=*(const float4*)(Wv + (size_t)(ct*128+oo)*CC + kc4);
    }
    float acc[4][4][4];
    #pragma unroll
    for(int a=0;a<4;a++)
        #pragma unroll
        for(int bq=0;bq<4;bq++)
            #pragma unroll
            for(int cq=0;cq<4;cq++) acc[a][bq][cq]=0.0f;

    for(int it=0; it<8; ++it){
        __syncthreads();
        #pragma unroll
        for(int l=0;l<4;l++){
            int f4=tid+l*256;
            int kk=f4>>5, n4=(f4&31)<<2;
            *(float4*)&As[kk][n4]=rA[l];
            int oo=f4>>3, kc=(f4&7)<<2;
            Bs[kc+0][oo]=__float_as_uint(rW[l].x); Bs[kc+1][oo]=__float_as_uint(rW[l].y);
            Bs[kc+2][oo]=__float_as_uint(rW[l].z); Bs[kc+3][oo]=__float_as_uint(rW[l].w);
        }
        __syncthreads();
        if(it+1<8){
            int c0=(it+1)*32;
            #pragma unroll
            for(int l=0;l<4;l++){
                int f4=tid+l*256;
                int kk=f4>>5, n4=(f4&31)<<2;
                rA[l]=*(const float4*)(x + ((size_t)b*CC + c0+kk)*NN + n0+n4);
                int oo=f4>>3, kc4=(f4&7)<<2;
                rW[l]=*(const float4*)(Wv + (size_t)(ct*128+oo)*CC + c0+kc4);
            }
        }
        mma_chunk(As,Bs,acc,m_base,c_base,lane);
    }
    #pragma unroll
    for(int mf=0;mf<4;mf++){
        int m = m_base + mf*16 + (lane>>2);
        #pragma unroll
        for(int nf=0;nf<4;nf++){
            int c = ct*128 + c_base + nf*8 + 2*(lane&3);
            float2 v0={acc[mf][nf][0],acc[mf][nf][1]};
            float2 v1={acc[mf][nf][2],acc[mf][nf][3]};
            *(float2*)&g_v[((size_t)b*NN + n0+m)*256 + c]   = v0;
            *(float2*)&g_v[((size_t)b*NN + n0+m+8)*256 + c] = v1;
        }
    }
}

// ---------------- feature maps (q_p, k_p) and geo RFF (phi) ----------------------
__global__ __launch_bounds__(128) void feat_kernel(const float* __restrict__ pos,
    const float* __restrict__ P,  const float* __restrict__ Wg1, const float* __restrict__ bg1,
    const float* __restrict__ Wg2,const float* __restrict__ bg2, const float* __restrict__ logtau,
    const float* __restrict__ omega)
{
    __shared__ float Ps[4096];
    __shared__ float Om[256];
    __shared__ float sWg1[48], sbg1[16], sWg2[256], sbg2[16];
    int tid=threadIdx.x;
    for(int i=tid;i<4096;i+=128) Ps[i]=P[i];
    for(int i=tid;i<256;i+=128){ Om[i]=omega[i]; sWg2[i]=Wg2[i]; }
    if(tid<48) sWg1[tid]=Wg1[tid];
    if(tid<16){ sbg1[tid]=bg1[tid]; sbg2[tid]=bg2[tid]; }
    __syncthreads();

    int b=blockIdx.y;
    int n=blockIdx.x*128 + tid;
    size_t bn=(size_t)b*NN + n;

    float lt=logtau[0];
    float tau=log1pf(expf(lt)) + 1e-6f;
    float s2t=sqrtf(2.0f*tau);
    float p0=pos[bn*3+0], p1=pos[bn*3+1], p2=pos[bn*3+2];
    float g1[16], z[16];
    #pragma unroll
    for(int d=0;d<16;d++){
        float t=fmaf(sWg1[d*3],p0,fmaf(sWg1[d*3+1],p1,fmaf(sWg1[d*3+2],p2,sbg1[d])));
        g1[d]=fmaxf(t,0.0f);
    }
    float zn=0.0f;
    #pragma unroll
    for(int d=0;d<16;d++){
        float t=sbg2[d];
        #pragma unroll
        for(int e=0;e<16;e++) t=fmaf(sWg2[d*16+e],g1[e],t);
        z[d]=t*s2t;
        zn=fmaf(z[d],z[d],zn);
    }
    zn*=0.5f;
    #pragma unroll
    for(int r=0;r<16;r++){
        float t=0.0f;
        #pragma unroll
        for(int d=0;d<16;d++) t=fmaf(z[d],Om[d*16+r],t);
        g_phi[bn*16+r]=expf(t-zn)*0.25f;
    }

    const float* row = g_qk + bn*128;
    const float fs = 0.08838834764831845f;
    for(int which=0;which<2;which++){
        const float* qr = row + which*64;
        float proj[64];
        #pragma unroll
        for(int m=0;m<64;m++) proj[m]=0.0f;
        for(int o=0;o<64;o++){
            float qo=qr[o];
            #pragma unroll
            for(int m=0;m<64;m++) proj[m]=fmaf(qo,Ps[o*64+m],proj[m]);
        }
        float M=0.0f;
        #pragma unroll
        for(int m=0;m<64;m++) M=fmaxf(M,fabsf(proj[m]));
        float* dst=(which==0? g_qp : g_kp) + bn*128;
        #pragma unroll
        for(int m=0;m<64;m++){
            dst[m]    = expf(proj[m]-M)*fs + 1e-6f;
            dst[64+m] = expf(-proj[m]-M)*fs + 1e-6f;
        }
    }
}

// ---------------- ksum: partial + reduce -----------------------------------------
__global__ __launch_bounds__(256) void ksum_part()
{
    __shared__ float skp[64][128];
    __shared__ float sph[64][16];
    int t=threadIdx.x;
    int ch=blockIdx.x, b=blockIdx.y;
    int nbase=ch*256;
    float acc[8]={};
    int iidx[8], jidx[8];
    #pragma unroll
    for(int k=0;k<8;k++){ int r=t+k*256; iidx[k]=r>>4; jidx[k]=r&15; }
    for(int sub=0;sub<4;sub++){
        int ns=nbase+sub*64;
        __syncthreads();
        #pragma unroll
        for(int l=0;l<8;l++){
            int f4=t+l*256; int row=f4>>5, c4=f4&31;
            *(float4*)&skp[row][c4*4]=*(const float4*)(g_kp+((size_t)b*NN+ns+row)*128+c4*4);
        }
        { int row=t>>2, c4=t&3;
          *(float4*)&sph[row][c4*4]=*(const float4*)(g_phi+((size_t)b*NN+ns+row)*16+c4*4); }
        __syncthreads();
        for(int n=0;n<64;n++){
            #pragma unroll
            for(int k=0;k<8;k++) acc[k]=fmaf(skp[n][iidx[k]],sph[n][jidx[k]],acc[k]);
        }
    }
    #pragma unroll
    for(int k=0;k<8;k++) g_kspart[((size_t)b*32+ch)*RR + t + k*256]=acc[k];
}

__global__ void ksum_reduce()
{
    int r=blockIdx.x*256+threadIdx.x; int b=blockIdx.y;
    float s=0.0f;
    #pragma unroll 8
    for(int c=0;c<32;c++) s+=g_kspart[((size_t)b*32+c)*RR + r];
    g_ksum[(size_t)b*RR + r]=s;
}

// ---------------- denom[b][n] = Phi_q[n]·k_sum + eps ------------------------------
__global__ __launch_bounds__(256) void denom_kernel()
{
    __shared__ float ks[2048];
    int b=blockIdx.y;
    for(int i=threadIdx.x;i<2048;i+=256) ks[i]=g_ksum[(size_t)b*RR+i];
    __syncthreads();
    int n=blockIdx.x*256 + threadIdx.x;
    size_t bn=(size_t)b*NN+n;
    float ph[16];
    #pragma unroll
    for(int r=0;r<16;r++) ph[r]=g_phi[bn*16+r];
    float d=0.0f;
    for(int i=0;i<128;i++){
        float t=0.0f;
        #pragma unroll
        for(int jj=0;jj<16;jj++) t=fmaf(ks[i*16+jj],ph[jj],t);
        d=fmaf(g_qp[bn*128+i],t,d);
    }
    g_denom[bn]=d+1e-6f;
}

// ================= tf32 mma GEMM 1: kv (split-K=2, CTA 128x256, cp.async) ========
// kvpart[b][sk][r][c] = sum_{n in half sk} (kp[n,i(r)]*phi[n,j(r)]) * v[n,c]
#define KVFSA_SMEM (2*32*136*4 + 2*32*264*4)   // 102400 bytes
__global__ void __launch_bounds__(256,1) kv_tf32()
{
    extern __shared__ uint32_t smu[];
    uint32_t (*As)[136] = (uint32_t(*)[136])smu;               // [2*32][136]
    uint32_t (*Bs)[264] = (uint32_t(*)[264])(smu + 2*32*136);  // [2*32][264]
    const int mt=blockIdx.x, sk=blockIdx.y, b=blockIdx.z;
    const int tid=threadIdx.x, lane=tid&31, wid=tid>>5;
    const int m_base=(wid>>2)*64, c_base=(wid&3)*64;
    const size_t bn=(size_t)b*NN;
    const int i0=mt*8;
    const int nstart = sk*4096;
    const int skk=tid>>3, si=tid&7;
    const uint32_t bB = smem_u32(&Bs[0][0]);

    // per-thread B-copy roles
    int browL[8], bc4L[8];
    #pragma unroll
    for(int l=0;l<8;l++){ int f4=tid+l*256; browL[l]=f4>>6; bc4L[l]=(f4&63)<<2; }

    // prologue: B(0) via cp.async, A regs(0)
    #pragma unroll
    for(int l=0;l<8;l++)
        cp16(bB + (uint32_t)((browL[l]*264 + bc4L[l])<<2),
             g_v + (bn+nstart+browL[l])*256 + bc4L[l]);
    CP_COMMIT();
    float rphi[16]; float rkp;
    {
        const float* ph=g_phi + (bn+nstart+skk)*16;
        #pragma unroll
        for(int q=0;q<4;q++) *(float4*)(rphi+q*4)=*(const float4*)(ph+q*4);
        rkp = g_kp[(bn+nstart+skk)*128 + i0+si];
    }
    float acc[4][8][4];
    #pragma unroll
    for(int a=0;a<4;a++)
        #pragma unroll
        for(int bq=0;bq<8;bq++)
            #pragma unroll
            for(int cq=0;cq<4;cq++) acc[a][bq][cq]=0.0f;

    for(int it=0; it<128; ++it){
        const int buf=(it&1)*32;
        // stage A(it) raw fp32 bits
        #pragma unroll
        for(int q=0;q<4;q++){
            uint4 u={__float_as_uint(rkp*rphi[q*4+0]),__float_as_uint(rkp*rphi[q*4+1]),
                     __float_as_uint(rkp*rphi[q*4+2]),__float_as_uint(rkp*rphi[q*4+3])};
            *(uint4*)&As[buf+skk][si*16+q*4]=u;
        }
        CP_WAIT0();           // B(it) arrived (only group in flight)
        __syncthreads();      // A(it)+B(it) visible; everyone past mma(it-1)
        if(it+1<128){
            const int n0=nstart+(it+1)*32;
            const uint32_t dst0 = bB + (uint32_t)(((it+1)&1)*32*264*4);
            #pragma unroll
            for(int l=0;l<8;l++)
                cp16(dst0 + (uint32_t)((browL[l]*264 + bc4L[l])<<2),
                     g_v + (bn+n0+browL[l])*256 + bc4L[l]);
            CP_COMMIT();
            const float* ph=g_phi + (bn+n0+skk)*16;
            #pragma unroll
            for(int q=0;q<4;q++) *(float4*)(rphi+q*4)=*(const float4*)(ph+q*4);
            rkp = g_kp[(bn+n0+skk)*128 + i0+si];
        }
        mma_chunk64(As+buf,Bs+buf,acc,m_base,c_base,lane);
    }
    float* dst = g_kvpart + ((size_t)b*2+sk)*RR*CC;
    #pragma unroll
    for(int mf=0;mf<4;mf++){
        int m = mt*128 + m_base + mf*16 + (lane>>2);
        #pragma unroll
        for(int nf=0;nf<8;nf++){
            int c = c_base + nf*8 + 2*(lane&3);
            float2 v0={acc[mf][nf][0],acc[mf][nf][1]};
            float2 v1={acc[mf][nf][2],acc[mf][nf][3]};
            *(float2*)&dst[(size_t)m*CC + c]     = v0;
            *(float2*)&dst[(size_t)(m+8)*CC + c] = v1;
        }
    }
}

// kv = part0 + part1
__global__ __launch_bounds__(256) void kv_reduce()
{
    size_t i4=(size_t)blockIdx.x*256 + threadIdx.x;
    size_t f=i4*4;
    size_t b=f/((size_t)RR*CC), off=f%((size_t)RR*CC);
    float4 a=*(const float4*)(g_kvpart + (b*2+0)*(size_t)RR*CC + off);
    float4 c=*(const float4*)(g_kvpart + (b*2+1)*(size_t)RR*CC + off);
    float4 o={a.x+c.x,a.y+c.y,a.z+c.z,a.w+c.w};
    *(float4*)(g_kv + b*(size_t)RR*CC + off)=o;
}

// ================= tf32 mma GEMM 2: fsa (CTA 128x256, cp.async) ==================
// fsa[b][n][c] = (sum_r (qp[n,i(r)]*phi[n,j(r)]) * kv[r,c]) / denom[n]
__global__ void __launch_bounds__(256,1) fsa_tf32()
{
    extern __shared__ uint32_t smu[];
    uint32_t (*As)[136] = (uint32_t(*)[136])smu;
    uint32_t (*Bs)[264] = (uint32_t(*)[264])(smu + 2*32*136);
    const int mt=blockIdx.x, b=blockIdx.z;
    const int tid=threadIdx.x, lane=tid&31, wid=tid>>5;
    const int m_base=(wid>>2)*64, c_base=(wid&3)*64;
    const size_t bn0=(size_t)b*NN + (size_t)mt*128;
    const float* kvbase = g_kv + (size_t)b*RR*CC;
    const int sm=tid>>1, sip=tid&1;
    const uint32_t bB = smem_u32(&Bs[0][0]);

    int browL[8], bc4L[8];
    #pragma unroll
    for(int l=0;l<8;l++){ int f4=tid+l*256; browL[l]=f4>>6; bc4L[l]=(f4&63)<<2; }

    float rphi[16];
    {
        const float* ph=g_phi + (bn0+sm)*16;
        #pragma unroll
        for(int q=0;q<4;q++) *(float4*)(rphi+q*4)=*(const float4*)(ph+q*4);
    }
    // prologue: B(0), A regs(0)
    #pragma unroll
    for(int l=0;l<8;l++)
        cp16(bB + (uint32_t)((browL[l]*264 + bc4L[l])<<2),
             kvbase + (size_t)browL[l]*CC + bc4L[l]);
    CP_COMMIT();
    float rqp = g_qp[(bn0+sm)*128 + sip];

    float acc[4][8][4];
    #pragma unroll
    for(int a=0;a<4;a++)
        #pragma unroll
        for(int bq=0;bq<8;bq++)
            #pragma unroll
            for(int cq=0;cq<4;cq++) acc[a][bq][cq]=0.0f;

    for(int it=0; it<64; ++it){
        const int buf=(it&1)*32;
        #pragma unroll
        for(int j=0;j<16;j++) As[buf+sip*16+j][sm]=__float_as_uint(rqp*rphi[j]);
        CP_WAIT0();
        __syncthreads();
        if(it+1<64){
            const int k0=(it+1)*32;
            const uint32_t dst0 = bB + (uint32_t)(((it+1)&1)*32*264*4);
            #pragma unroll
            for(int l=0;l<8;l++)
                cp16(dst0 + (uint32_t)((browL[l]*264 + bc4L[l])<<2),
                     kvbase + (size_t)(k0+browL[l])*CC + bc4L[l]);
            CP_COMMIT();
            rqp = g_qp[(bn0+sm)*128 + (it+1)*2 + sip];
        }
        mma_chunk64(As+buf,Bs+buf,acc,m_base,c_base,lane);
    }
    #pragma unroll
    for(int mf=0;mf<4;mf++){
        int ml = m_base + mf*16 + (lane>>2);
        float inv0 = 1.0f/g_denom[bn0+ml];
        float inv1 = 1.0f/g_denom[bn0+ml+8];
        #pragma unroll
        for(int nf=0;nf<8;nf++){
            int c = c_base + nf*8 + 2*(lane&3);
            float2 v0={acc[mf][nf][0]*inv0,acc[mf][nf][1]*inv0};
            float2 v1={acc[mf][nf][2]*inv1,acc[mf][nf][3]*inv1};
            *(float2*)&g_fsa[(bn0+ml)*CC + c]   = v0;
            *(float2*)&g_fsa[(bn0+ml+8)*CC + c] = v1;
        }
    }
}

// ---------------- h = Wp @ (x - fsa^T) (tf32 mma) + BN partials -------------------
__global__ __launch_bounds__(256) void h_tf32(const float* __restrict__ x, const float* __restrict__ Wp)
{
    __shared__ uint32_t As[32][136];   // [k=c][o] Wp (raw bits)
    __shared__ uint32_t Bs[32][136];   // [k=c][n] (x - fsa) (raw bits)
    __shared__ float red[128][5];
    const int mt=blockIdx.x, nt=blockIdx.y, b=blockIdx.z;
    const int o0=mt*128, n0=nt*128;
    const int tid=threadIdx.x, lane=tid&31, wid=tid>>5;
    const int m_base=(wid>>2)*64, c_base=(wid&3)*32;

    float4 rW[4], rF[4], rX[4];
    #pragma unroll
    for(int l=0;l<4;l++){
        int f4=tid+l*256;
        int oo=f4>>3, kc4=(f4&7)<<2;
        rW[l]=*(const float4*)(Wp + (size_t)(o0+oo)*CC + kc4);
        rF[l]=*(const float4*)(g_fsa + ((size_t)b*NN+n0+oo)*CC + kc4);
        int kk=f4>>5, n4=(f4&31)<<2;
        rX[l]=*(const float4*)(x + ((size_t)b*CC+kk)*NN + n0+n4);
    }
    float acc[4][4][4];
    #pragma unroll
    for(int a=0;a<4;a++)
        #pragma unroll
        for(int bq=0;bq<4;bq++)
            #pragma unroll
            for(int cq=0;cq<4;cq++) acc[a][bq][cq]=0.0f;

    for(int it=0; it<8; ++it){
        __syncthreads();
        #pragma unroll
        for(int l=0;l<4;l++){
            int f4=tid+l*256;
            int oo=f4>>3, kc=(f4&7)<<2;
            As[kc+0][oo]=__float_as_uint(rW[l].x); As[kc+1][oo]=__float_as_uint(rW[l].y);
            As[kc+2][oo]=__float_as_uint(rW[l].z); As[kc+3][oo]=__float_as_uint(rW[l].w);
            Bs[kc+0][oo]=__float_as_uint(-rF[l].x); Bs[kc+1][oo]=__float_as_uint(-rF[l].y);
            Bs[kc+2][oo]=__float_as_uint(-rF[l].z); Bs[kc+3][oo]=__float_as_uint(-rF[l].w);
        }
        __syncthreads();
        #pragma unroll
        for(int l=0;l<4;l++){
            int f4=tid+l*256;
            int kk=f4>>5, n4=(f4&31)<<2;
            uint4 cur=*(uint4*)&Bs[kk][n4];
            cur.x=__float_as_uint(__uint_as_float(cur.x)+rX[l].x);
            cur.y=__float_as_uint(__uint_as_float(cur.y)+rX[l].y);
            cur.z=__float_as_uint(__uint_as_float(cur.z)+rX[l].z);
            cur.w=__float_as_uint(__uint_as_float(cur.w)+rX[l].w);
            *(uint4*)&Bs[kk][n4]=cur;
        }
        __syncthreads();
        if(it+1<8){
            int c0=(it+1)*32;
            #pragma unroll
            for(int l=0;l<4;l++){
                int f4=tid+l*256;
                int oo=f4>>3, kc4=(f4&7)<<2;
                rW[l]=*(const float4*)(Wp + (size_t)(o0+oo)*CC + c0+kc4);
                rF[l]=*(const float4*)(g_fsa + ((size_t)b*NN+n0+oo)*CC + c0+kc4);
                int kk=f4>>5, n4=(f4&31)<<2;
                rX[l]=*(const float4*)(x + ((size_t)b*CC+c0+kk)*NN + n0+n4);
            }
        }
        mma_chunk(As,Bs,acc,m_base,c_base,lane);
    }
    #pragma unroll
    for(int mf=0;mf<4;mf++){
        int r0 = m_base + mf*16 + (lane>>2);
        #pragma unroll
        for(int nf=0;nf<4;nf++){
            int nl = c_base + nf*8 + 2*(lane&3);
            float2 v0={acc[mf][nf][0],acc[mf][nf][1]};
            float2 v1={acc[mf][nf][2],acc[mf][nf][3]};
            *(float2*)&g_h[((size_t)b*CC + o0+r0)*NN + n0+nl]   = v0;
            *(float2*)&g_h[((size_t)b*CC + o0+r0+8)*NN + n0+nl] = v1;
        }
    }
    float s[4][2], q2[4][2];
    #pragma unroll
    for(int mf=0;mf<4;mf++){
        float a0=0.f,a1=0.f,b0=0.f,b1=0.f;
        #pragma unroll
        for(int nf=0;nf<4;nf++){
            a0+=acc[mf][nf][0]+acc[mf][nf][1];
            b0+=acc[mf][nf][0]*acc[mf][nf][0]+acc[mf][nf][1]*acc[mf][nf][1];
            a1+=acc[mf][nf][2]+acc[mf][nf][3];
            b1+=acc[mf][nf][2]*acc[mf][nf][2]+acc[mf][nf][3]*acc[mf][nf][3];
        }
        s[mf][0]=a0; s[mf][1]=a1; q2[mf][0]=b0; q2[mf][1]=b1;
    }
    #pragma unroll
    for(int mf=0;mf<4;mf++)
        #pragma unroll
        for(int hh=0;hh<2;hh++){
            s[mf][hh]  += __shfl_xor_sync(0xffffffff, s[mf][hh], 1);
            s[mf][hh]  += __shfl_xor_sync(0xffffffff, s[mf][hh], 2);
            q2[mf][hh] += __shfl_xor_sync(0xffffffff, q2[mf][hh], 1);
            q2[mf][hh] += __shfl_xor_sync(0xffffffff, q2[mf][hh], 2);
        }
    __syncthreads();
    if((lane&3)==0){
        #pragma unroll
        for(int mf=0;mf<4;mf++)
            #pragma unroll
            for(int hh=0;hh<2;hh++)
                red[m_base+mf*16+(lane>>2)+hh*8][wid&3]=s[mf][hh];
    }
    __syncthreads();
    if(tid<128){
        float t=red[tid][0]+red[tid][1]+red[tid][2]+red[tid][3];
        g_psum[((size_t)b*NTILES+nt)*CC + o0 + tid]=t;
    }
    __syncthreads();
    if((lane&3)==0){
        #pragma unroll
        for(int mf=0;mf<4;mf++)
            #pragma unroll
            for(int hh=0;hh<2;hh++)
                red[m_base+mf*16+(lane>>2)+hh*8][wid&3]=q2[mf][hh];
    }
    __syncthreads();
    if(tid<128){
        float t=red[tid][0]+red[tid][1]+red[tid][2]+red[tid][3];
        g_psumsq[((size_t)b*NTILES+nt)*CC + o0 + tid]=t;
    }
}

// ---------------- BN stats -> scale/bias ------------------------------------------
__global__ void stats_kernel(const float* __restrict__ gamma, const float* __restrict__ beta)
{
    int o=threadIdx.x;
    float s=0.f,s2=0.f;
    for(int t=0;t<BB*NTILES;t++){
        s +=g_psum  [(size_t)t*CC+o];
        s2+=g_psumsq[(size_t)t*CC+o];
    }
    const float inv=1.0f/(float)((size_t)BB*NN);
    float mean=s*inv;
    float var=s2*inv - mean*mean;
    float sc=gamma[o]*rsqrtf(var+1e-5f);
    g_scale[o]=sc;
    g_bias[o]=beta[o]-mean*sc;
}

// ---------------- out = relu(BN(h)) + x --------------------------------------------
__global__ __launch_bounds__(256) void final_kernel(const float* __restrict__ x, float* __restrict__ out)
{
    size_t i4=(size_t)blockIdx.x*256 + threadIdx.x;
    size_t f=i4*4;
    int c=(int)((f/NN)%CC);
    float sc=g_scale[c], bi=g_bias[c];
    float4 h=*(const float4*)(g_h+f);
    float4 xv=*(const float4*)(x+f);
    float4 o;
    o.x=fmaxf(fmaf(h.x,sc,bi),0.0f)+xv.x;
    o.y=fmaxf(fmaf(h.y,sc,bi),0.0f)+xv.y;
    o.z=fmaxf(fmaf(h.z,sc,bi),0.0f)+xv.z;
    o.w=fmaxf(fmaf(h.w,sc,bi),0.0f)+xv.w;
    *(float4*)(out+f)=o;
}

// ---------------- launch ------------------------------------------------------------
extern "C" void kernel_launch(void* const* d_in, const int* in_sizes, int n_in,
                              void* d_out, int out_size)
{
    const float* x      =(const float*)d_in[0];
    const float* pos    =(const float*)d_in[1];
    const float* Wq     =(const float*)d_in[2];
    const float* Wk     =(const float*)d_in[3];
    const float* Wv     =(const float*)d_in[4];
    const float* proj_sm=(const float*)d_in[5];
    const float* Wg1    =(const float*)d_in[6];
    const float* bg1    =(const float*)d_in[7];
    const float* Wg2    =(const float*)d_in[8];
    const float* bg2    =(const float*)d_in[9];
    const float* log_tau=(const float*)d_in[10];
    const float* omega  =(const float*)d_in[11];
    const float* Wp     =(const float*)d_in[12];
    const float* gamma  =(const float*)d_in[13];
    const float* beta   =(const float*)d_in[14];
    float* out=(float*)d_out;

    static int smem_set = 0;
    if(!smem_set){
        cudaFuncSetAttribute(kv_tf32,  cudaFuncAttributeMaxDynamicSharedMemorySize, KVFSA_SMEM);
        cudaFuncSetAttribute(fsa_tf32, cudaFuncAttributeMaxDynamicSharedMemorySize, KVFSA_SMEM);
        smem_set = 1;
    }

    qk_gemm     <<<dim3(64,BB),256>>>(x,Wq,Wk);                                      // 0
    v_tf32      <<<dim3(64,2,BB),256>>>(x,Wv);                                       // 1
    feat_kernel <<<dim3(64,BB),128>>>(pos,proj_sm,Wg1,bg1,Wg2,bg2,log_tau,omega);    // 2
    kv_tf32     <<<dim3(16,2,BB),256,KVFSA_SMEM>>>();                                // 3 (ncu slot)
    kv_reduce   <<<2048,256>>>();                                                    // 4
    ksum_part   <<<dim3(32,BB),256>>>();                                             // 5
    ksum_reduce <<<dim3(8,BB),256>>>();                                              // 6
    denom_kernel<<<dim3(32,BB),256>>>();                                             // 7
    fsa_tf32    <<<dim3(64,1,BB),256,KVFSA_SMEM>>>();                                // 8
    h_tf32      <<<dim3(2,64,BB),256>>>(x,Wp);                                       // 9
    stats_kernel<<<1,256>>>(gamma,beta);                                             // 10
    final_kernel<<<8192,256>>>(x,out);                                               // 11
}